// round 12
// baseline (speedup 1.0000x reference)
#include <cuda_runtime.h>
#include <cuda_fp16.h>
#include <float.h>
#include <math.h>
#include <stdint.h>

// Problem constants
#define BSZ   2
#define NN    1024
#define EE    2048
#define LTOT  3072
#define DIMN  128
#define EDIM  256
#define HEADS 8
#define DHEAD 64
#define INNER 512
#define SCALE 0.125f
#define LOG2E 1.4426950408889634f
#define NB_N  8                                 // node colsum chunks per batch
#define NB_E  16                                // edge colsum chunks per batch

// Scratch (fp16 intermediates)
__device__ __half g_qh[BSZ * HEADS * LTOT * DHEAD];   // pre-scaled by SCALE*LOG2E
__device__ __half g_kh[BSZ * HEADS * LTOT * DHEAD];
__device__ __half g_vh[BSZ * HEADS * LTOT * DHEAD];
__device__ __half g_oh[BSZ * LTOT * INNER];
__device__ int    g_mask[BSZ * LTOT];
__device__ int    g_kidx[BSZ * LTOT];                 // compacted unmasked indices
__device__ int    g_nk[BSZ];
__device__ float  g_csn[BSZ * NB_N * DIMN];           // node column-sum partials
__device__ float  g_cse[BSZ * NB_E * EDIM];           // edge column-sum partials
__device__ float  g_vms[BSZ * INNER];                 // Vmean per (b, col)

// ---------------------------------------------------------------------------
// PTX helpers
// ---------------------------------------------------------------------------
__device__ __forceinline__ uint32_t sptr(const void* p) {
    return (uint32_t)__cvta_generic_to_shared(p);
}
__device__ __forceinline__ void ldsm_x4(uint32_t& r0, uint32_t& r1,
                                        uint32_t& r2, uint32_t& r3, uint32_t addr) {
    asm volatile("ldmatrix.sync.aligned.m8n8.x4.shared.b16 {%0,%1,%2,%3}, [%4];"
                 : "=r"(r0), "=r"(r1), "=r"(r2), "=r"(r3) : "r"(addr));
}
__device__ __forceinline__ void ldsm_x4_t(uint32_t& r0, uint32_t& r1,
                                          uint32_t& r2, uint32_t& r3, uint32_t addr) {
    asm volatile("ldmatrix.sync.aligned.m8n8.x4.trans.shared.b16 {%0,%1,%2,%3}, [%4];"
                 : "=r"(r0), "=r"(r1), "=r"(r2), "=r"(r3) : "r"(addr));
}
__device__ __forceinline__ void mma_f16(float c[4],
                                        uint32_t a0, uint32_t a1, uint32_t a2, uint32_t a3,
                                        uint32_t b0, uint32_t b1) {
    asm volatile(
        "mma.sync.aligned.m16n8k16.row.col.f32.f16.f16.f32 "
        "{%0,%1,%2,%3}, {%4,%5,%6,%7}, {%8,%9}, {%0,%1,%2,%3};"
        : "+f"(c[0]), "+f"(c[1]), "+f"(c[2]), "+f"(c[3])
        : "r"(a0), "r"(a1), "r"(a2), "r"(a3), "r"(b0), "r"(b1));
}
__device__ __forceinline__ void cp16(uint32_t dst, const void* src) {
    asm volatile("cp.async.cg.shared.global [%0], [%1], 16;" :: "r"(dst), "l"(src));
}
__device__ __forceinline__ void cp_commit() {
    asm volatile("cp.async.commit_group;");
}
__device__ __forceinline__ void cp_wait0() {
    asm volatile("cp.async.wait_group 0;");
}
__device__ __forceinline__ uint32_t packh2(float x, float y) {
    __half2 h = __floats2half2_rn(x, y);
    return *reinterpret_cast<uint32_t*>(&h);
}
__device__ __forceinline__ float fexp2(float x) {
    float y;
    asm("ex2.approx.ftz.f32 %0, %1;" : "=f"(y) : "f"(x));
    return y;
}

// ---------------------------------------------------------------------------
// Mask decode + per-batch compaction of unmasked indices.
// ---------------------------------------------------------------------------
__global__ void mask_kernel(const unsigned char* __restrict__ raw) {
    __shared__ int partial[256];
    __shared__ int pfx[256];
    const int n = BSZ * LTOT;
    const int b = blockIdx.x;
    const int tid = threadIdx.x;

    int cnt = 0;
    for (int i = tid; i < n; i += 256) cnt += (raw[i] != 0);
    partial[tid] = cnt;
    __syncthreads();
    for (int s = 128; s > 0; s >>= 1) {
        if (tid < s) partial[tid] += partial[tid + s];
        __syncthreads();
    }
    const int width1 = partial[0] > (n * 3 / 8);
    const int* raw32 = (const int*)raw;

    int bits[12];
    int myc = 0;
    #pragma unroll
    for (int i = 0; i < 12; i++) {
        int li = tid * 12 + i;
        int gi = b * LTOT + li;
        int v = width1 ? (raw[gi] != 0) : (raw32[gi] != 0);
        g_mask[gi] = v;
        bits[i] = v;
        myc += v;
    }
    pfx[tid] = myc;
    __syncthreads();
    if (tid == 0) {
        int acc = 0;
        for (int t = 0; t < 256; t++) { int c = pfx[t]; pfx[t] = acc; acc += c; }
        g_nk[b] = acc;
    }
    __syncthreads();
    int off = b * LTOT + pfx[tid];
    #pragma unroll
    for (int i = 0; i < 12; i++)
        if (bits[i]) g_kidx[off++] = tid * 12 + i;
}

// ---------------------------------------------------------------------------
// Column-sum partials of raw inputs (for the linear Vmean identity:
// sum_l V[l] = colsum(nodes)@Wv + N*bv + colsum(edges)@Wev + E*bev).
// grid = 48: [0,16) node chunks, [16,48) edge chunks. Deterministic order.
// ---------------------------------------------------------------------------
__global__ __launch_bounds__(256) void colsum_kernel(
        const float* __restrict__ nodes, const float* __restrict__ edges) {
    const int t = blockIdx.x;
    const int tid = threadIdx.x;
    if (t < 16) {
        const int b = t >> 3, ch = t & 7;
        const float* src = nodes + ((size_t)b * NN + ch * 128) * DIMN;
        const int c = tid & 127, half = tid >> 7;
        float s = 0.f;
        for (int r = half; r < 128; r += 2) s += src[(size_t)r * DIMN + c];
        __shared__ float sm[256];
        sm[tid] = s;
        __syncthreads();
        if (half == 0) g_csn[(b * NB_N + ch) * DIMN + c] = sm[c] + sm[128 + c];
    } else {
        const int u = t - 16;
        const int b = u >> 4, ch = u & 15;
        const float* src = edges + ((size_t)b * EE + ch * 128) * EDIM;
        float s = 0.f;
        for (int r = 0; r < 128; r++) s += src[(size_t)r * EDIM + tid];
        g_cse[(b * NB_E + ch) * EDIM + tid] = s;
    }
}

// ---------------------------------------------------------------------------
// Vmean GEMV: g_vms[b][col] = (colsum(nodes)@Wv + N*bv + colsum(edges)@Wev
//  + E*bev)[col] / LTOT. grid = BSZ, 512 threads (thread = col). Coalesced
// W-row loads, independent iterations (MLP-pipelined).
// ---------------------------------------------------------------------------
__global__ __launch_bounds__(512) void vmeanlin_kernel(
        const float* __restrict__ Wv, const float* __restrict__ bv,
        const float* __restrict__ Wev, const float* __restrict__ bev) {
    const int b = blockIdx.x;
    const int col = threadIdx.x;                 // 0..511
    __shared__ float csn[DIMN];
    __shared__ float cse[EDIM];

    if (col < DIMN) {
        float s = 0.f;
        #pragma unroll
        for (int k = 0; k < NB_N; k++) s += g_csn[(b * NB_N + k) * DIMN + col];
        csn[col] = s;
    } else if (col < DIMN + EDIM) {
        const int c = col - DIMN;
        float s = 0.f;
        #pragma unroll
        for (int k = 0; k < NB_E; k++) s += g_cse[(b * NB_E + k) * EDIM + c];
        cse[c] = s;
    }
    __syncthreads();

    float acc = (float)NN * bv[col] + (float)EE * bev[col];
    #pragma unroll 4
    for (int c = 0; c < DIMN; c++) acc += csn[c] * Wv[(size_t)c * INNER + col];
    #pragma unroll 4
    for (int c = 0; c < EDIM; c++) acc += cse[c] * Wev[(size_t)c * INNER + col];
    g_vms[b * INNER + col] = acc * (1.0f / LTOT);
}

// ---------------------------------------------------------------------------
// GEMM body (device fn): C = (A' @ W + bias) * scale, 128x64 tile, BK=32.
// ---------------------------------------------------------------------------
template <bool AHALF, int DSTMODE>
__device__ __forceinline__ void gemm_body(
        const void* __restrict__ Ap, const float* __restrict__ W,
        const float* __restrict__ bias, void* __restrict__ dst, float scl,
        int K, int Ncols, int rowsPerBatch, int aBatchStride, int aSeqOff,
        int dstSeqOff, int row0, int col0) {
    __shared__ __align__(16) __half sA[128 * 40];
    __shared__ __align__(16) __half sW[32 * 72];

    const int tid = threadIdx.x;
    const int warp = tid >> 5, lane = tid & 31;
    const int g = lane >> 2, qd = lane & 3;
    const int wy = warp >> 1, wx = warp & 1;

    const uint32_t uA = sptr(sA);
    const uint32_t uW = sptr(sW);
    const int offA = ((lane & 7) + ((lane >> 3) & 1) * 8) * 80 + (lane >> 4) * 16;
    const int offW = ((lane & 7) + ((lane >> 3) & 1) * 8) * 144 + (lane >> 4) * 16;

    float acc[2][4][4] = {};

    for (int kt = 0; kt < K; kt += 32) {
        #pragma unroll
        for (int t = 0; t < 8; t++) {
            int idx = tid + t * 256;
            int i = idx >> 4, k2 = idx & 15;
            int m = row0 + i;
            int bb = m / rowsPerBatch;
            int r = m - bb * rowsPerBatch;
            size_t arow = (size_t)(bb * aBatchStride + aSeqOff + r) * K + kt + 2 * k2;
            if (AHALF) {
                ((__half2*)sA)[i * 20 + k2] = *(const __half2*)((const __half*)Ap + arow);
            } else {
                float2 v = *(const float2*)((const float*)Ap + arow);
                ((__half2*)sA)[i * 20 + k2] = __floats2half2_rn(v.x, v.y);
            }
        }
        #pragma unroll
        for (int t = 0; t < 4; t++) {
            int idx = tid + t * 256;
            int kr = idx >> 5, n2 = idx & 31;
            float2 v = *(const float2*)&W[(size_t)(kt + kr) * Ncols + col0 + 2 * n2];
            ((__half2*)sW)[kr * 36 + n2] = __floats2half2_rn(v.x, v.y);
        }
        __syncthreads();

        #pragma unroll
        for (int kk = 0; kk < 2; kk++) {
            uint32_t a[2][4];
            #pragma unroll
            for (int mt = 0; mt < 2; mt++)
                ldsm_x4(a[mt][0], a[mt][1], a[mt][2], a[mt][3],
                        uA + (wy * 32 + mt * 16) * 80 + kk * 32 + offA);
            #pragma unroll
            for (int p = 0; p < 2; p++) {
                uint32_t b0, b1, b2, b3;
                ldsm_x4_t(b0, b1, b2, b3,
                          uW + kk * 16 * 144 + (wx * 32 + p * 16) * 2 + offW);
                mma_f16(acc[0][2 * p],     a[0][0], a[0][1], a[0][2], a[0][3], b0, b1);
                mma_f16(acc[0][2 * p + 1], a[0][0], a[0][1], a[0][2], a[0][3], b2, b3);
                mma_f16(acc[1][2 * p],     a[1][0], a[1][1], a[1][2], a[1][3], b0, b1);
                mma_f16(acc[1][2 * p + 1], a[1][0], a[1][1], a[1][2], a[1][3], b2, b3);
            }
        }
        __syncthreads();
    }

    #pragma unroll
    for (int mt = 0; mt < 2; mt++) {
        #pragma unroll
        for (int hh = 0; hh < 2; hh++) {
            int m = row0 + wy * 32 + mt * 16 + g + 8 * hh;
            int bb = m / rowsPerBatch;
            int r = m - bb * rowsPerBatch;
            #pragma unroll
            for (int n = 0; n < 4; n++) {
                int c = col0 + wx * 32 + n * 8 + 2 * qd;
                float v0 = (acc[mt][n][hh * 2 + 0] + bias[c]) * scl;
                float v1 = (acc[mt][n][hh * 2 + 1] + bias[c + 1]) * scl;
                if (DSTMODE == 0) {
                    int hidx = c >> 6, d = c & 63;
                    __half* dh = (__half*)dst;
                    *(__half2*)&dh[((size_t)(bb * HEADS + hidx) * LTOT +
                                    dstSeqOff + r) * DHEAD + d] = __floats2half2_rn(v0, v1);
                } else {
                    float* df = (float*)dst;
                    *(float2*)&df[(size_t)m * Ncols + c] = make_float2(v0, v1);
                }
            }
        }
    }
}

// ---------------------------------------------------------------------------
// Fused QKV projections (node + edge, all six GEMMs) in one launch.
// ---------------------------------------------------------------------------
__global__ __launch_bounds__(256) void qkv_kernel(
        const float* __restrict__ nodes, const float* __restrict__ edges,
        const float* Wq, const float* Wk, const float* Wv,
        const float* bq, const float* bk, const float* bv,
        const float* Weq, const float* Wek, const float* Wev,
        const float* beq, const float* bek, const float* bev,
        __half* qp, __half* kp, __half* vp, float qscale) {
    const int t = blockIdx.x;
    if (t < 384) {
        const int z = t / 128, r = t % 128;
        const int col0 = (r & 7) * 64, row0 = (r >> 3) * 128;
        const float* W    = (z == 0) ? Wq : (z == 1) ? Wk : Wv;
        const float* bias = (z == 0) ? bq : (z == 1) ? bk : bv;
        __half* dst       = (z == 0) ? qp : (z == 1) ? kp : vp;
        const float scl   = (z == 0) ? qscale : 1.f;
        gemm_body<false, 0>(nodes, W, bias, dst, scl,
                            128, 512, 1024, 1024, 0, 0, row0, col0);
    } else {
        const int u = t - 384;
        const int z = u / 256, r = u % 256;
        const int col0 = (r & 7) * 64, row0 = (r >> 3) * 128;
        const float* W    = (z == 0) ? Weq : (z == 1) ? Wek : Wev;
        const float* bias = (z == 0) ? beq : (z == 1) ? bek : bev;
        __half* dst       = (z == 0) ? qp : (z == 1) ? kp : vp;
        const float scl   = (z == 0) ? qscale : 1.f;
        gemm_body<false, 0>(edges, W, bias, dst, scl,
                            256, 512, 2048, 2048, 0, 1024, row0, col0);
    }
}

// ---------------------------------------------------------------------------
// Fused output projections (node + edge) in one launch. 160 CTAs.
// ---------------------------------------------------------------------------
__global__ __launch_bounds__(256) void outproj_kernel(
        const float* __restrict__ Wo, const float* __restrict__ bo,
        const float* __restrict__ Weo, const float* __restrict__ beo,
        float* __restrict__ out) {
    const int t = blockIdx.x;
    if (t < 32) {
        const int col0 = (t & 1) * 64, row0 = (t >> 1) * 128;
        gemm_body<true, 1>(g_oh, Wo, bo, out, 1.f,
                           512, 128, 1024, 3072, 0, 0, row0, col0);
    } else {
        const int u = t - 32;
        const int col0 = (u & 3) * 64, row0 = (u >> 2) * 128;
        gemm_body<true, 1>(g_oh, Weo, beo, out + 2 * 1024 * 128, 1.f,
                           512, 256, 2048, 3072, 1024, 0, row0, col0);
    }
}

// ---------------------------------------------------------------------------
// Flash attention over compacted rows (queries AND keys), Br=128, 256 thr.
// Idle CTAs (q0 >= nk) patch masked rows of g_oh from the precomputed
// Vmean table g_vms. Disjoint row sets -> no race.
// ---------------------------------------------------------------------------
#define KVSTR 72
#define KVBUF_H (64 * KVSTR)
#define KVBUF_B (KVBUF_H * 2)
#define ATTN_SMEM_BYTES (4 * KVBUF_B)

__device__ __forceinline__ void patch_tiles(int b, int h, int pstart, int pstep) {
    const int tid = threadIdx.x;
    const int dg = tid & 7;
    const float* vm = g_vms + b * INNER + h * DHEAD + dg * 8;
    uint4 hv;
    hv.x = packh2(vm[0], vm[1]);
    hv.y = packh2(vm[2], vm[3]);
    hv.z = packh2(vm[4], vm[5]);
    hv.w = packh2(vm[6], vm[7]);
    for (int p = pstart; p < 24; p += pstep) {
        #pragma unroll
        for (int pass = 0; pass < 4; pass++) {
            int r = p * 128 + pass * 32 + (tid >> 3);
            if (!g_mask[b * LTOT + r])
                *(uint4*)&g_oh[(size_t)(b * LTOT + r) * INNER + h * DHEAD + dg * 8] = hv;
        }
    }
}

__global__ __launch_bounds__(256, 2) void attn_f16_kernel() {
    const int bh = blockIdx.y;
    const int b = bh >> 3, h = bh & 7;
    const int nk = g_nk[b];
    const int q0 = blockIdx.x * 128;
    const int qtiles = (nk + 127) >> 7;
    const int nidle = 24 - qtiles;

    if (q0 >= nk) {
        patch_tiles(b, h, blockIdx.x - qtiles, nidle);
        return;
    }

    extern __shared__ __align__(16) char smraw[];
    __half* Kh = (__half*)smraw;                 // [2][64][72]
    __half* Vh = (__half*)(smraw + 2 * KVBUF_B); // [2][64][72]

    const int tid = threadIdx.x;
    const int warp = tid >> 5, lane = tid & 31;
    const int g = lane >> 2, qd = lane & 3;

    const __half* Qg = g_qh + (size_t)bh * LTOT * DHEAD;
    const __half* Kg = g_kh + (size_t)bh * LTOT * DHEAD;
    const __half* Vg = g_vh + (size_t)bh * LTOT * DHEAD;
    const int* kidx = g_kidx + b * LTOT;
    const int NIT = (nk + 63) >> 6;

    const uint32_t uK = sptr(Kh), uV = sptr(Vh);
    const int offA = ((lane & 7) + ((lane >> 3) & 1) * 8) * 144 + (lane >> 4) * 16;
    const int offK = ((lane & 7) + ((lane >> 4) & 1) * 8) * 144 + ((lane >> 3) & 1) * 16;

    const int prow = tid >> 3;                   // 0..31
    const int pch = (tid & 7) * 16;              // byte offset 0..112

    // Prologue: gather-load tile 0
    {
        #pragma unroll
        for (int rr = 0; rr < 2; rr++) {
            int r = prow + rr * 32;
            int idx = (r < nk) ? kidx[r] : 0;
            cp16(uK + r * 144 + pch, Kg + (size_t)idx * 64 + (pch >> 1));
            cp16(uV + r * 144 + pch, Vg + (size_t)idx * 64 + (pch >> 1));
        }
        cp_commit();
    }

    // Query rows (gathered)
    const int qr_a = q0 + warp * 16 + g;
    const int qr_b = qr_a + 8;
    const int valid0 = qr_a < nk;
    const int valid1 = qr_b < nk;
    const int qi0 = valid0 ? kidx[qr_a] : kidx[0];
    const int qi1 = valid1 ? kidx[qr_b] : kidx[0];

    uint32_t qa[4][4];
    {
        const __half* qr0p = Qg + (size_t)qi0 * DHEAD;
        const __half* qr1p = Qg + (size_t)qi1 * DHEAD;
        #pragma unroll
        for (int kk = 0; kk < 4; kk++) {
            int c = kk * 16 + 2 * qd;
            qa[kk][0] = *(const uint32_t*)(qr0p + c);
            qa[kk][1] = *(const uint32_t*)(qr1p + c);
            qa[kk][2] = *(const uint32_t*)(qr0p + c + 8);
            qa[kk][3] = *(const uint32_t*)(qr1p + c + 8);
        }
    }

    float m_i[2] = {-FLT_MAX, -FLT_MAX};
    float l_i[2] = {0.f, 0.f};
    float o[8][4] = {};

    for (int it = 0; it < NIT; it++) {
        const int bf = it & 1;
        const int k0 = it * 64;
        cp_wait0();
        __syncthreads();

        if (it + 1 < NIT) {
            uint32_t uKn = uK + (bf ^ 1) * KVBUF_B;
            uint32_t uVn = uV + (bf ^ 1) * KVBUF_B;
            #pragma unroll
            for (int rr = 0; rr < 2; rr++) {
                int r = prow + rr * 32;
                int gi = k0 + 64 + r;
                int idx = (gi < nk) ? kidx[gi] : 0;
                cp16(uKn + r * 144 + pch, Kg + (size_t)idx * 64 + (pch >> 1));
                cp16(uVn + r * 144 + pch, Vg + (size_t)idx * 64 + (pch >> 1));
            }
            cp_commit();
        }

        const uint32_t uKb = uK + bf * KVBUF_B;
        const uint32_t uVb = uV + bf * KVBUF_B;

        // ---- S = Q @ K^T ----
        float s[8][4] = {};
        #pragma unroll
        for (int kk = 0; kk < 4; kk++) {
            #pragma unroll
            for (int p = 0; p < 4; p++) {
                uint32_t b0, b1, b2, b3;
                ldsm_x4(b0, b1, b2, b3, uKb + p * 16 * 144 + kk * 32 + offK);
                mma_f16(s[2 * p],     qa[kk][0], qa[kk][1], qa[kk][2], qa[kk][3], b0, b1);
                mma_f16(s[2 * p + 1], qa[kk][0], qa[kk][1], qa[kk][2], qa[kk][3], b2, b3);
            }
        }

        // ---- tail masking (key side) ----
        if (k0 + 64 > nk) {
            #pragma unroll
            for (int nt = 0; nt < 8; nt++) {
                int j0 = k0 + nt * 8 + 2 * qd;
                if (j0 >= nk)     { s[nt][0] = -FLT_MAX; s[nt][2] = -FLT_MAX; }
                if (j0 + 1 >= nk) { s[nt][1] = -FLT_MAX; s[nt][3] = -FLT_MAX; }
            }
        }

        // ---- online softmax (base-2) ----
        #pragma unroll
        for (int hh = 0; hh < 2; hh++) {
            float mx = -FLT_MAX;
            #pragma unroll
            for (int nt = 0; nt < 8; nt++)
                mx = fmaxf(mx, fmaxf(s[nt][hh * 2], s[nt][hh * 2 + 1]));
            mx = fmaxf(mx, __shfl_xor_sync(0xffffffffu, mx, 1));
            mx = fmaxf(mx, __shfl_xor_sync(0xffffffffu, mx, 2));
            float mnew = fmaxf(m_i[hh], mx);
            float corr = fexp2(m_i[hh] - mnew);
            m_i[hh] = mnew;
            float rs = 0.f;
            #pragma unroll
            for (int nt = 0; nt < 8; nt++) {
                float p0 = fexp2(s[nt][hh * 2]     - mnew);
                float p1 = fexp2(s[nt][hh * 2 + 1] - mnew);
                rs += p0 + p1;
                s[nt][hh * 2]     = p0;
                s[nt][hh * 2 + 1] = p1;
            }
            rs += __shfl_xor_sync(0xffffffffu, rs, 1);
            rs += __shfl_xor_sync(0xffffffffu, rs, 2);
            l_i[hh] = l_i[hh] * corr + rs;
            #pragma unroll
            for (int nt = 0; nt < 8; nt++) {
                o[nt][hh * 2]     *= corr;
                o[nt][hh * 2 + 1] *= corr;
            }
        }

        // ---- O += P @ V ----
        #pragma unroll
        for (int jj = 0; jj < 4; jj++) {
            uint32_t pa0 = packh2(s[2 * jj][0],     s[2 * jj][1]);
            uint32_t pa1 = packh2(s[2 * jj][2],     s[2 * jj][3]);
            uint32_t pa2 = packh2(s[2 * jj + 1][0], s[2 * jj + 1][1]);
            uint32_t pa3 = packh2(s[2 * jj + 1][2], s[2 * jj + 1][3]);
            #pragma unroll
            for (int p = 0; p < 4; p++) {
                uint32_t b0, b1, b2, b3;
                ldsm_x4_t(b0, b1, b2, b3, uVb + jj * 16 * 144 + p * 32 + offA);
                mma_f16(o[2 * p],     pa0, pa1, pa2, pa3, b0, b1);
                mma_f16(o[2 * p + 1], pa0, pa1, pa2, pa3, b2, b3);
            }
        }
    }

    // ---- epilogue: normalize + scatter to original row indices ----
    #pragma unroll
    for (int hh = 0; hh < 2; hh++) {
        if (!(hh ? valid1 : valid0)) continue;
        const int qrow = hh ? qi1 : qi0;
        float inv = 1.f / l_i[hh];
        __half* dstp = &g_oh[(size_t)(b * LTOT + qrow) * INNER + h * DHEAD];
        #pragma unroll
        for (int nt = 0; nt < 8; nt++) {
            int d0 = nt * 8 + 2 * qd;
            *(__half2*)&dstp[d0] =
                __floats2half2_rn(o[nt][hh * 2] * inv, o[nt][hh * 2 + 1] * inv);
        }
    }

    // Fallback: if no idle CTAs exist (nk > 2944), last CTA patches everything.
    if (nidle == 0 && blockIdx.x == 23) {
        __syncthreads();
        patch_tiles(b, h, 0, 1);
    }
}

// ---------------------------------------------------------------------------
// kernel_launch
// ---------------------------------------------------------------------------
extern "C" void kernel_launch(void* const* d_in, const int* in_sizes, int n_in,
                              void* d_out, int out_size) {
    const float* nodes = (const float*)d_in[0];
    const float* edges = (const float*)d_in[1];
    const unsigned char* mask_raw = (const unsigned char*)d_in[2];
    const float* Wq  = (const float*)d_in[3];
    const float* bq  = (const float*)d_in[4];
    const float* Wk  = (const float*)d_in[5];
    const float* bk  = (const float*)d_in[6];
    const float* Wv  = (const float*)d_in[7];
    const float* bv  = (const float*)d_in[8];
    const float* Weq = (const float*)d_in[9];
    const float* beq = (const float*)d_in[10];
    const float* Wek = (const float*)d_in[11];
    const float* bek = (const float*)d_in[12];
    const float* Wev = (const float*)d_in[13];
    const float* bev = (const float*)d_in[14];
    const float* Wo  = (const float*)d_in[15];
    const float* bo  = (const float*)d_in[16];
    const float* Weo = (const float*)d_in[17];
    const float* beo = (const float*)d_in[18];
    float* out = (float*)d_out;

    void *qp, *kp, *vp;
    cudaGetSymbolAddress(&qp, g_qh);
    cudaGetSymbolAddress(&kp, g_kh);
    cudaGetSymbolAddress(&vp, g_vh);

    mask_kernel<<<BSZ, 256>>>(mask_raw);

    // Input column sums, then Vmean via the linear identity
    colsum_kernel<<<48, 256>>>(nodes, edges);
    vmeanlin_kernel<<<BSZ, 512>>>(Wv, bv, Wev, bev);

    // All six QKV projections in one launch
    qkv_kernel<<<1152, 256>>>(
        nodes, edges, Wq, Wk, Wv, bq, bk, bv,
        Weq, Wek, Wev, beq, bek, bev,
        (__half*)qp, (__half*)kp, (__half*)vp, SCALE * LOG2E);

    // Flash attention (Br=128) + Vmean patch in idle CTAs
    cudaFuncSetAttribute(attn_f16_kernel,
                         cudaFuncAttributeMaxDynamicSharedMemorySize, ATTN_SMEM_BYTES);
    attn_f16_kernel<<<dim3(24, BSZ * HEADS), 256, ATTN_SMEM_BYTES>>>();

    // Both output projections in one launch
    outproj_kernel<<<160, 256>>>(Wo, bo, Weo, beo, out);
}

// round 13
// speedup vs baseline: 1.2235x; 1.2235x over previous
#include <cuda_runtime.h>
#include <cuda_fp16.h>
#include <float.h>
#include <math.h>
#include <stdint.h>

// Problem constants
#define BSZ   2
#define NN    1024
#define EE    2048
#define LTOT  3072
#define DIMN  128
#define EDIM  256
#define HEADS 8
#define DHEAD 64
#define INNER 512
#define SCALE 0.125f
#define LOG2E 1.4426950408889634f
#define NCH   16                                // vmean chunks per (b,h)

// Scratch (fp16 intermediates)
__device__ __half g_qh[BSZ * HEADS * LTOT * DHEAD];   // COMPACTED rows, pre-scaled
__device__ __half g_kh[BSZ * HEADS * LTOT * DHEAD];   // COMPACTED rows
__device__ __half g_vh[BSZ * HEADS * LTOT * DHEAD];   // full (vmean needs all rows)
__device__ __half g_oh[BSZ * LTOT * INNER];
__device__ int    g_mask[BSZ * LTOT];
__device__ int    g_kidx[BSZ * LTOT];                 // compacted unmasked indices
__device__ int    g_nk[BSZ];                          // total unmasked
__device__ int    g_nn[BSZ];                          // unmasked among nodes (<1024)
__device__ float  g_vpart[BSZ * HEADS * NCH * DHEAD]; // partial V sums

// ---------------------------------------------------------------------------
// PTX helpers
// ---------------------------------------------------------------------------
__device__ __forceinline__ uint32_t sptr(const void* p) {
    return (uint32_t)__cvta_generic_to_shared(p);
}
__device__ __forceinline__ void ldsm_x4(uint32_t& r0, uint32_t& r1,
                                        uint32_t& r2, uint32_t& r3, uint32_t addr) {
    asm volatile("ldmatrix.sync.aligned.m8n8.x4.shared.b16 {%0,%1,%2,%3}, [%4];"
                 : "=r"(r0), "=r"(r1), "=r"(r2), "=r"(r3) : "r"(addr));
}
__device__ __forceinline__ void ldsm_x4_t(uint32_t& r0, uint32_t& r1,
                                          uint32_t& r2, uint32_t& r3, uint32_t addr) {
    asm volatile("ldmatrix.sync.aligned.m8n8.x4.trans.shared.b16 {%0,%1,%2,%3}, [%4];"
                 : "=r"(r0), "=r"(r1), "=r"(r2), "=r"(r3) : "r"(addr));
}
__device__ __forceinline__ void mma_f16(float c[4],
                                        uint32_t a0, uint32_t a1, uint32_t a2, uint32_t a3,
                                        uint32_t b0, uint32_t b1) {
    asm volatile(
        "mma.sync.aligned.m16n8k16.row.col.f32.f16.f16.f32 "
        "{%0,%1,%2,%3}, {%4,%5,%6,%7}, {%8,%9}, {%0,%1,%2,%3};"
        : "+f"(c[0]), "+f"(c[1]), "+f"(c[2]), "+f"(c[3])
        : "r"(a0), "r"(a1), "r"(a2), "r"(a3), "r"(b0), "r"(b1));
}
__device__ __forceinline__ void cp16(uint32_t dst, const void* src) {
    asm volatile("cp.async.cg.shared.global [%0], [%1], 16;" :: "r"(dst), "l"(src));
}
__device__ __forceinline__ void cp_commit() {
    asm volatile("cp.async.commit_group;");
}
__device__ __forceinline__ void cp_wait0() {
    asm volatile("cp.async.wait_group 0;");
}
__device__ __forceinline__ uint32_t packh2(float x, float y) {
    __half2 h = __floats2half2_rn(x, y);
    return *reinterpret_cast<uint32_t*>(&h);
}
__device__ __forceinline__ float fexp2(float x) {
    float y;
    asm("ex2.approx.ftz.f32 %0, %1;" : "=f"(y) : "f"(x));
    return y;
}

// ---------------------------------------------------------------------------
// Mask decode + per-batch compaction (also counts node-region unmasked).
// ---------------------------------------------------------------------------
__global__ void mask_kernel(const unsigned char* __restrict__ raw) {
    __shared__ int partial[256];
    __shared__ int pfx[256];
    __shared__ int pnode[256];
    const int n = BSZ * LTOT;
    const int b = blockIdx.x;
    const int tid = threadIdx.x;

    int cnt = 0;
    for (int i = tid; i < n; i += 256) cnt += (raw[i] != 0);
    partial[tid] = cnt;
    __syncthreads();
    for (int s = 128; s > 0; s >>= 1) {
        if (tid < s) partial[tid] += partial[tid + s];
        __syncthreads();
    }
    const int width1 = partial[0] > (n * 3 / 8);
    const int* raw32 = (const int*)raw;

    int bits[12];
    int myc = 0, mync = 0;
    #pragma unroll
    for (int i = 0; i < 12; i++) {
        int li = tid * 12 + i;
        int gi = b * LTOT + li;
        int v = width1 ? (raw[gi] != 0) : (raw32[gi] != 0);
        g_mask[gi] = v;
        bits[i] = v;
        myc += v;
        if (li < NN) mync += v;
    }
    pfx[tid] = myc;
    pnode[tid] = mync;
    __syncthreads();
    for (int s = 128; s > 0; s >>= 1) {
        if (tid < s) pnode[tid] += pnode[tid + s];
        __syncthreads();
    }
    if (tid == 0) {
        g_nn[b] = pnode[0];
        int acc = 0;
        for (int t = 0; t < 256; t++) { int c = pfx[t]; pfx[t] = acc; acc += c; }
        g_nk[b] = acc;
    }
    __syncthreads();
    int off = b * LTOT + pfx[tid];
    #pragma unroll
    for (int i = 0; i < 12; i++)
        if (bits[i]) g_kidx[off++] = tid * 12 + i;
}

// ---------------------------------------------------------------------------
// Partial V sums (R8 version): grid = BSZ*HEADS*NCH, chunks of 192 rows.
// ---------------------------------------------------------------------------
__global__ void vmean_kernel() {
    const int bh = blockIdx.x / NCH;
    const int chunk = blockIdx.x % NCH;
    const int CROWS = LTOT / NCH;                // 192
    const __half* Vg = g_vh + (size_t)bh * LTOT * DHEAD + (size_t)chunk * CROWS * DHEAD;
    const int tid = threadIdx.x;
    const int rg = tid >> 3;
    const int dg = tid & 7;

    float acc[8] = {};
    for (int r = rg; r < CROWS; r += 32) {
        uint4 u = *(const uint4*)(Vg + (size_t)r * DHEAD + dg * 8);
        const __half2* h2 = (const __half2*)&u;
        #pragma unroll
        for (int j = 0; j < 4; j++) {
            float2 f = __half22float2(h2[j]);
            acc[2 * j]     += f.x;
            acc[2 * j + 1] += f.y;
        }
    }

    __shared__ float sm[256][8];
    #pragma unroll
    for (int j = 0; j < 8; j++) sm[tid][j] = acc[j];
    __syncthreads();

    if (tid < DHEAD) {
        int d = tid;
        int srcdg = d >> 3, j = d & 7;
        float s = 0.f;
        #pragma unroll
        for (int r = 0; r < 32; r++) s += sm[srcdg + 8 * r][j];
        g_vpart[(bh * NCH + chunk) * DHEAD + d] = s;
    }
}

// ---------------------------------------------------------------------------
// Dense GEMM body (V projection + output projections), as in R8.
// ---------------------------------------------------------------------------
template <bool AHALF, int DSTMODE>
__device__ __forceinline__ void gemm_body(
        const void* __restrict__ Ap, const float* __restrict__ W,
        const float* __restrict__ bias, void* __restrict__ dst, float scl,
        int K, int Ncols, int rowsPerBatch, int aBatchStride, int aSeqOff,
        int dstSeqOff, int row0, int col0) {
    __shared__ __align__(16) __half sA[128 * 40];
    __shared__ __align__(16) __half sW[32 * 72];

    const int tid = threadIdx.x;
    const int warp = tid >> 5, lane = tid & 31;
    const int g = lane >> 2, qd = lane & 3;
    const int wy = warp >> 1, wx = warp & 1;

    const uint32_t uA = sptr(sA);
    const uint32_t uW = sptr(sW);
    const int offA = ((lane & 7) + ((lane >> 3) & 1) * 8) * 80 + (lane >> 4) * 16;
    const int offW = ((lane & 7) + ((lane >> 3) & 1) * 8) * 144 + (lane >> 4) * 16;

    float acc[2][4][4] = {};

    for (int kt = 0; kt < K; kt += 32) {
        #pragma unroll
        for (int t = 0; t < 8; t++) {
            int idx = tid + t * 256;
            int i = idx >> 4, k2 = idx & 15;
            int m = row0 + i;
            int bb = m / rowsPerBatch;
            int r = m - bb * rowsPerBatch;
            size_t arow = (size_t)(bb * aBatchStride + aSeqOff + r) * K + kt + 2 * k2;
            if (AHALF) {
                ((__half2*)sA)[i * 20 + k2] = *(const __half2*)((const __half*)Ap + arow);
            } else {
                float2 v = *(const float2*)((const float*)Ap + arow);
                ((__half2*)sA)[i * 20 + k2] = __floats2half2_rn(v.x, v.y);
            }
        }
        #pragma unroll
        for (int t = 0; t < 4; t++) {
            int idx = tid + t * 256;
            int kr = idx >> 5, n2 = idx & 31;
            float2 v = *(const float2*)&W[(size_t)(kt + kr) * Ncols + col0 + 2 * n2];
            ((__half2*)sW)[kr * 36 + n2] = __floats2half2_rn(v.x, v.y);
        }
        __syncthreads();

        #pragma unroll
        for (int kk = 0; kk < 2; kk++) {
            uint32_t a[2][4];
            #pragma unroll
            for (int mt = 0; mt < 2; mt++)
                ldsm_x4(a[mt][0], a[mt][1], a[mt][2], a[mt][3],
                        uA + (wy * 32 + mt * 16) * 80 + kk * 32 + offA);
            #pragma unroll
            for (int p = 0; p < 2; p++) {
                uint32_t b0, b1, b2, b3;
                ldsm_x4_t(b0, b1, b2, b3,
                          uW + kk * 16 * 144 + (wx * 32 + p * 16) * 2 + offW);
                mma_f16(acc[0][2 * p],     a[0][0], a[0][1], a[0][2], a[0][3], b0, b1);
                mma_f16(acc[0][2 * p + 1], a[0][0], a[0][1], a[0][2], a[0][3], b2, b3);
                mma_f16(acc[1][2 * p],     a[1][0], a[1][1], a[1][2], a[1][3], b0, b1);
                mma_f16(acc[1][2 * p + 1], a[1][0], a[1][1], a[1][2], a[1][3], b2, b3);
            }
        }
        __syncthreads();
    }

    #pragma unroll
    for (int mt = 0; mt < 2; mt++) {
        #pragma unroll
        for (int hh = 0; hh < 2; hh++) {
            int m = row0 + wy * 32 + mt * 16 + g + 8 * hh;
            int bb = m / rowsPerBatch;
            int r = m - bb * rowsPerBatch;
            #pragma unroll
            for (int n = 0; n < 4; n++) {
                int c = col0 + wx * 32 + n * 8 + 2 * qd;
                float v0 = (acc[mt][n][hh * 2 + 0] + bias[c]) * scl;
                float v1 = (acc[mt][n][hh * 2 + 1] + bias[c + 1]) * scl;
                if (DSTMODE == 0) {
                    int hidx = c >> 6, d = c & 63;
                    __half* dh = (__half*)dst;
                    *(__half2*)&dh[((size_t)(bb * HEADS + hidx) * LTOT +
                                    dstSeqOff + r) * DHEAD + d] = __floats2half2_rn(v0, v1);
                } else {
                    float* df = (float*)dst;
                    *(float2*)&df[(size_t)m * Ncols + c] = make_float2(v0, v1);
                }
            }
        }
    }
}

// ---------------------------------------------------------------------------
// Compacted-row GEMM for Q/K projections: gathers A rows via kidx (segment
// [slot0, segEnd) is uniformly node or edge), writes to compacted slot rows
// in dst ([B,H,slot,DHEAD] layout). Rows beyond segEnd: computed on row 0,
// not stored.
// ---------------------------------------------------------------------------
__device__ __forceinline__ void gemm_qk_compact(
        const float* __restrict__ A,          // batch-offset source base
        const float* __restrict__ W, const float* __restrict__ bias,
        __half* __restrict__ dst, float scl, int K, int srcOff,
        const int* __restrict__ kidx,         // batch-offset
        int slot0, int segEnd, int bhBase, int col0) {
    __shared__ __align__(16) __half sA[128 * 40];
    __shared__ __align__(16) __half sW[32 * 72];

    const int tid = threadIdx.x;
    const int warp = tid >> 5, lane = tid & 31;
    const int g = lane >> 2, qd = lane & 3;
    const int wy = warp >> 1, wx = warp & 1;

    const uint32_t uA = sptr(sA);
    const uint32_t uW = sptr(sW);
    const int offA = ((lane & 7) + ((lane >> 3) & 1) * 8) * 80 + (lane >> 4) * 16;
    const int offW = ((lane & 7) + ((lane >> 3) & 1) * 8) * 144 + (lane >> 4) * 16;

    float acc[2][4][4] = {};

    for (int kt = 0; kt < K; kt += 32) {
        #pragma unroll
        for (int t = 0; t < 8; t++) {
            int idx = tid + t * 256;
            int i = idx >> 4, k2 = idx & 15;
            int slot = slot0 + i;
            int src = (slot < segEnd) ? (kidx[slot] - srcOff) : 0;
            float2 v = *(const float2*)&A[(size_t)src * K + kt + 2 * k2];
            ((__half2*)sA)[i * 20 + k2] = __floats2half2_rn(v.x, v.y);
        }
        #pragma unroll
        for (int t = 0; t < 4; t++) {
            int idx = tid + t * 256;
            int kr = idx >> 5, n2 = idx & 31;
            float2 v = *(const float2*)&W[(size_t)(kt + kr) * INNER + col0 + 2 * n2];
            ((__half2*)sW)[kr * 36 + n2] = __floats2half2_rn(v.x, v.y);
        }
        __syncthreads();

        #pragma unroll
        for (int kk = 0; kk < 2; kk++) {
            uint32_t a[2][4];
            #pragma unroll
            for (int mt = 0; mt < 2; mt++)
                ldsm_x4(a[mt][0], a[mt][1], a[mt][2], a[mt][3],
                        uA + (wy * 32 + mt * 16) * 80 + kk * 32 + offA);
            #pragma unroll
            for (int p = 0; p < 2; p++) {
                uint32_t b0, b1, b2, b3;
                ldsm_x4_t(b0, b1, b2, b3,
                          uW + kk * 16 * 144 + (wx * 32 + p * 16) * 2 + offW);
                mma_f16(acc[0][2 * p],     a[0][0], a[0][1], a[0][2], a[0][3], b0, b1);
                mma_f16(acc[0][2 * p + 1], a[0][0], a[0][1], a[0][2], a[0][3], b2, b3);
                mma_f16(acc[1][2 * p],     a[1][0], a[1][1], a[1][2], a[1][3], b0, b1);
                mma_f16(acc[1][2 * p + 1], a[1][0], a[1][1], a[1][2], a[1][3], b2, b3);
            }
        }
        __syncthreads();
    }

    #pragma unroll
    for (int mt = 0; mt < 2; mt++) {
        #pragma unroll
        for (int hh = 0; hh < 2; hh++) {
            int slot = slot0 + wy * 32 + mt * 16 + g + 8 * hh;
            bool ok = slot < segEnd;
            #pragma unroll
            for (int n = 0; n < 4; n++) {
                int c = col0 + wx * 32 + n * 8 + 2 * qd;
                float v0 = (acc[mt][n][hh * 2 + 0] + bias[c]) * scl;
                float v1 = (acc[mt][n][hh * 2 + 1] + bias[c + 1]) * scl;
                if (ok) {
                    int hidx = c >> 6, d = c & 63;
                    *(__half2*)&dst[((size_t)(bhBase + hidx) * LTOT + slot) * DHEAD + d] =
                        __floats2half2_rn(v0, v1);
                }
            }
        }
    }
}

// ---------------------------------------------------------------------------
// Fused QKV projections: Q/K over COMPACTED rows, V over all rows.
// 1152 CTAs: [0,256) node Q/K, [256,768) edge Q/K, [768,1152) V dense.
// ---------------------------------------------------------------------------
__global__ __launch_bounds__(256) void qkv_kernel(
        const float* __restrict__ nodes, const float* __restrict__ edges,
        const float* Wq, const float* Wk, const float* Wv,
        const float* bq, const float* bk, const float* bv,
        const float* Weq, const float* Wek, const float* Wev,
        const float* beq, const float* bek, const float* bev,
        __half* qp, __half* kp, __half* vp, float qscale) {
    const int t = blockIdx.x;
    if (t < 256) {
        // node Q/K: pr(2) x b(2) x rt(8) x ct(8)
        const int pr = t >> 7;
        const int rem = t & 127;
        const int b = rem >> 6;
        const int rt = (rem >> 3) & 7;
        const int ct = rem & 7;
        const int nn = g_nn[b];
        const int slot0 = rt * 128;
        if (slot0 >= nn) return;
        gemm_qk_compact(nodes + (size_t)b * NN * DIMN,
                        pr ? Wk : Wq, pr ? bk : bq, pr ? kp : qp,
                        pr ? 1.f : qscale, DIMN, 0,
                        g_kidx + b * LTOT, slot0, nn, b * HEADS, ct * 64);
    } else if (t < 768) {
        // edge Q/K: pr(2) x b(2) x rt(16) x ct(8)
        const int u = t - 256;
        const int pr = u >> 8;
        const int rem = u & 255;
        const int b = rem >> 7;
        const int rt = (rem >> 3) & 15;
        const int ct = rem & 7;
        const int nn = g_nn[b];
        const int nk = g_nk[b];
        const int slot0 = nn + rt * 128;
        if (slot0 >= nk) return;
        gemm_qk_compact(edges + (size_t)b * EE * EDIM,
                        pr ? Wek : Weq, pr ? bek : beq, pr ? kp : qp,
                        pr ? 1.f : qscale, EDIM, NN,
                        g_kidx + b * LTOT, slot0, nk, b * HEADS, ct * 64);
    } else {
        // V dense: node 128 CTAs, edge 256 CTAs (as in R8)
        const int u = t - 768;
        if (u < 128) {
            const int row0 = (u >> 3) * 128, col0 = (u & 7) * 64;
            gemm_body<false, 0>(nodes, Wv, bv, vp, 1.f,
                                128, 512, 1024, 1024, 0, 0, row0, col0);
        } else {
            const int v = u - 128;
            const int row0 = (v >> 3) * 128, col0 = (v & 7) * 64;
            gemm_body<false, 0>(edges, Wev, bev, vp, 1.f,
                                256, 512, 2048, 2048, 0, 1024, row0, col0);
        }
    }
}

// ---------------------------------------------------------------------------
// Fused output projections (node + edge) in one launch. 160 CTAs.
// ---------------------------------------------------------------------------
__global__ __launch_bounds__(256) void outproj_kernel(
        const float* __restrict__ Wo, const float* __restrict__ bo,
        const float* __restrict__ Weo, const float* __restrict__ beo,
        float* __restrict__ out) {
    const int t = blockIdx.x;
    if (t < 32) {
        const int col0 = (t & 1) * 64, row0 = (t >> 1) * 128;
        gemm_body<true, 1>(g_oh, Wo, bo, out, 1.f,
                           512, 128, 1024, 3072, 0, 0, row0, col0);
    } else {
        const int u = t - 32;
        const int col0 = (u & 3) * 64, row0 = (u >> 2) * 128;
        gemm_body<true, 1>(g_oh, Weo, beo, out + 2 * 1024 * 128, 1.f,
                           512, 256, 2048, 3072, 1024, 0, row0, col0);
    }
}

// ---------------------------------------------------------------------------
// Flash attention over compacted rows. Q/K now stored compacted (dense
// reads); V gathered via kidx; output scattered via kidx. Idle CTAs patch
// masked rows of g_oh from g_vpart (uniform softmax = Vmean).
// ---------------------------------------------------------------------------
#define KVSTR 72
#define KVBUF_H (64 * KVSTR)
#define KVBUF_B (KVBUF_H * 2)
#define ATTN_SMEM_BYTES (4 * KVBUF_B)

__device__ __forceinline__ void patch_tiles(int b, int h, int bh, int pstart, int pstep) {
    __shared__ float vms[64];
    const int tid = threadIdx.x;
    if (tid < 64) {
        float s = 0.f;
        #pragma unroll
        for (int c = 0; c < NCH; c++) s += g_vpart[(bh * NCH + c) * DHEAD + tid];
        vms[tid] = s * (1.0f / LTOT);
    }
    __syncthreads();
    const int dg = tid & 7;
    uint4 hv;
    hv.x = packh2(vms[dg * 8 + 0], vms[dg * 8 + 1]);
    hv.y = packh2(vms[dg * 8 + 2], vms[dg * 8 + 3]);
    hv.z = packh2(vms[dg * 8 + 4], vms[dg * 8 + 5]);
    hv.w = packh2(vms[dg * 8 + 6], vms[dg * 8 + 7]);
    for (int p = pstart; p < 24; p += pstep) {
        #pragma unroll
        for (int pass = 0; pass < 4; pass++) {
            int r = p * 128 + pass * 32 + (tid >> 3);
            if (!g_mask[b * LTOT + r])
                *(uint4*)&g_oh[(size_t)(b * LTOT + r) * INNER + h * DHEAD + dg * 8] = hv;
        }
    }
}

__global__ __launch_bounds__(256, 2) void attn_f16_kernel() {
    const int bh = blockIdx.y;
    const int b = bh >> 3, h = bh & 7;
    const int nk = g_nk[b];
    const int q0 = blockIdx.x * 128;
    const int qtiles = (nk + 127) >> 7;
    const int nidle = 24 - qtiles;

    if (q0 >= nk) {
        patch_tiles(b, h, bh, blockIdx.x - qtiles, nidle);
        return;
    }

    extern __shared__ __align__(16) char smraw[];
    __half* Kh = (__half*)smraw;                 // [2][64][72]
    __half* Vh = (__half*)(smraw + 2 * KVBUF_B); // [2][64][72]

    const int tid = threadIdx.x;
    const int warp = tid >> 5, lane = tid & 31;
    const int g = lane >> 2, qd = lane & 3;

    const __half* Qg = g_qh + (size_t)bh * LTOT * DHEAD;   // compacted
    const __half* Kg = g_kh + (size_t)bh * LTOT * DHEAD;   // compacted
    const __half* Vg = g_vh + (size_t)bh * LTOT * DHEAD;   // full
    const int* kidx = g_kidx + b * LTOT;
    const int NIT = (nk + 63) >> 6;

    const uint32_t uK = sptr(Kh), uV = sptr(Vh);
    const int offA = ((lane & 7) + ((lane >> 3) & 1) * 8) * 144 + (lane >> 4) * 16;
    const int offK = ((lane & 7) + ((lane >> 4) & 1) * 8) * 144 + ((lane >> 3) & 1) * 16;

    const int prow = tid >> 3;                   // 0..31
    const int pch = (tid & 7) * 16;              // byte offset 0..112

    // Prologue: load tile 0 (K dense, V gathered)
    {
        #pragma unroll
        for (int rr = 0; rr < 2; rr++) {
            int r = prow + rr * 32;
            int kdrow = (r < nk) ? r : 0;
            int vrow = (r < nk) ? kidx[r] : 0;
            cp16(uK + r * 144 + pch, Kg + (size_t)kdrow * 64 + (pch >> 1));
            cp16(uV + r * 144 + pch, Vg + (size_t)vrow * 64 + (pch >> 1));
        }
        cp_commit();
    }

    // Query rows: dense compacted slots
    const int qr_a = q0 + warp * 16 + g;
    const int qr_b = qr_a + 8;
    const int valid0 = qr_a < nk;
    const int valid1 = qr_b < nk;

    uint32_t qa[4][4];
    {
        const __half* qr0p = Qg + (size_t)(valid0 ? qr_a : 0) * DHEAD;
        const __half* qr1p = Qg + (size_t)(valid1 ? qr_b : 0) * DHEAD;
        #pragma unroll
        for (int kk = 0; kk < 4; kk++) {
            int c = kk * 16 + 2 * qd;
            qa[kk][0] = *(const uint32_t*)(qr0p + c);
            qa[kk][1] = *(const uint32_t*)(qr1p + c);
            qa[kk][2] = *(const uint32_t*)(qr0p + c + 8);
            qa[kk][3] = *(const uint32_t*)(qr1p + c + 8);
        }
    }

    float m_i[2] = {-FLT_MAX, -FLT_MAX};
    float l_i[2] = {0.f, 0.f};
    float o[8][4] = {};

    for (int it = 0; it < NIT; it++) {
        const int bf = it & 1;
        const int k0 = it * 64;
        cp_wait0();
        __syncthreads();

        if (it + 1 < NIT) {
            uint32_t uKn = uK + (bf ^ 1) * KVBUF_B;
            uint32_t uVn = uV + (bf ^ 1) * KVBUF_B;
            #pragma unroll
            for (int rr = 0; rr < 2; rr++) {
                int r = prow + rr * 32;
                int gi = k0 + 64 + r;
                int kdrow = (gi < nk) ? gi : 0;
                int vrow = (gi < nk) ? kidx[gi] : 0;
                cp16(uKn + r * 144 + pch, Kg + (size_t)kdrow * 64 + (pch >> 1));
                cp16(uVn + r * 144 + pch, Vg + (size_t)vrow * 64 + (pch >> 1));
            }
            cp_commit();
        }

        const uint32_t uKb = uK + bf * KVBUF_B;
        const uint32_t uVb = uV + bf * KVBUF_B;

        // ---- S = Q @ K^T ----
        float s[8][4] = {};
        #pragma unroll
        for (int kk = 0; kk < 4; kk++) {
            #pragma unroll
            for (int p = 0; p < 4; p++) {
                uint32_t b0, b1, b2, b3;
                ldsm_x4(b0, b1, b2, b3, uKb + p * 16 * 144 + kk * 32 + offK);
                mma_f16(s[2 * p],     qa[kk][0], qa[kk][1], qa[kk][2], qa[kk][3], b0, b1);
                mma_f16(s[2 * p + 1], qa[kk][0], qa[kk][1], qa[kk][2], qa[kk][3], b2, b3);
            }
        }

        // ---- tail masking (key side) ----
        if (k0 + 64 > nk) {
            #pragma unroll
            for (int nt = 0; nt < 8; nt++) {
                int j0 = k0 + nt * 8 + 2 * qd;
                if (j0 >= nk)     { s[nt][0] = -FLT_MAX; s[nt][2] = -FLT_MAX; }
                if (j0 + 1 >= nk) { s[nt][1] = -FLT_MAX; s[nt][3] = -FLT_MAX; }
            }
        }

        // ---- online softmax (base-2) ----
        #pragma unroll
        for (int hh = 0; hh < 2; hh++) {
            float mx = -FLT_MAX;
            #pragma unroll
            for (int nt = 0; nt < 8; nt++)
                mx = fmaxf(mx, fmaxf(s[nt][hh * 2], s[nt][hh * 2 + 1]));
            mx = fmaxf(mx, __shfl_xor_sync(0xffffffffu, mx, 1));
            mx = fmaxf(mx, __shfl_xor_sync(0xffffffffu, mx, 2));
            float mnew = fmaxf(m_i[hh], mx);
            float corr = fexp2(m_i[hh] - mnew);
            m_i[hh] = mnew;
            float rs = 0.f;
            #pragma unroll
            for (int nt = 0; nt < 8; nt++) {
                float p0 = fexp2(s[nt][hh * 2]     - mnew);
                float p1 = fexp2(s[nt][hh * 2 + 1] - mnew);
                rs += p0 + p1;
                s[nt][hh * 2]     = p0;
                s[nt][hh * 2 + 1] = p1;
            }
            rs += __shfl_xor_sync(0xffffffffu, rs, 1);
            rs += __shfl_xor_sync(0xffffffffu, rs, 2);
            l_i[hh] = l_i[hh] * corr + rs;
            #pragma unroll
            for (int nt = 0; nt < 8; nt++) {
                o[nt][hh * 2]     *= corr;
                o[nt][hh * 2 + 1] *= corr;
            }
        }

        // ---- O += P @ V ----
        #pragma unroll
        for (int jj = 0; jj < 4; jj++) {
            uint32_t pa0 = packh2(s[2 * jj][0],     s[2 * jj][1]);
            uint32_t pa1 = packh2(s[2 * jj][2],     s[2 * jj][3]);
            uint32_t pa2 = packh2(s[2 * jj + 1][0], s[2 * jj + 1][1]);
            uint32_t pa3 = packh2(s[2 * jj + 1][2], s[2 * jj + 1][3]);
            #pragma unroll
            for (int p = 0; p < 4; p++) {
                uint32_t b0, b1, b2, b3;
                ldsm_x4_t(b0, b1, b2, b3, uVb + jj * 16 * 144 + p * 32 + offA);
                mma_f16(o[2 * p],     pa0, pa1, pa2, pa3, b0, b1);
                mma_f16(o[2 * p + 1], pa0, pa1, pa2, pa3, b2, b3);
            }
        }
    }

    // ---- epilogue: normalize + scatter to original row indices ----
    #pragma unroll
    for (int hh = 0; hh < 2; hh++) {
        if (!(hh ? valid1 : valid0)) continue;
        const int qrow = kidx[hh ? qr_b : qr_a];
        float inv = 1.f / l_i[hh];
        __half* dstp = &g_oh[(size_t)(b * LTOT + qrow) * INNER + h * DHEAD];
        #pragma unroll
        for (int nt = 0; nt < 8; nt++) {
            int d0 = nt * 8 + 2 * qd;
            *(__half2*)&dstp[d0] =
                __floats2half2_rn(o[nt][hh * 2] * inv, o[nt][hh * 2 + 1] * inv);
        }
    }

    // Fallback: if no idle CTAs exist (nk > 2944), last CTA patches everything.
    if (nidle == 0 && blockIdx.x == 23) {
        __syncthreads();
        patch_tiles(b, h, bh, 0, 1);
    }
}

// ---------------------------------------------------------------------------
// kernel_launch
// ---------------------------------------------------------------------------
extern "C" void kernel_launch(void* const* d_in, const int* in_sizes, int n_in,
                              void* d_out, int out_size) {
    const float* nodes = (const float*)d_in[0];
    const float* edges = (const float*)d_in[1];
    const unsigned char* mask_raw = (const unsigned char*)d_in[2];
    const float* Wq  = (const float*)d_in[3];
    const float* bq  = (const float*)d_in[4];
    const float* Wk  = (const float*)d_in[5];
    const float* bk  = (const float*)d_in[6];
    const float* Wv  = (const float*)d_in[7];
    const float* bv  = (const float*)d_in[8];
    const float* Weq = (const float*)d_in[9];
    const float* beq = (const float*)d_in[10];
    const float* Wek = (const float*)d_in[11];
    const float* bek = (const float*)d_in[12];
    const float* Wev = (const float*)d_in[13];
    const float* bev = (const float*)d_in[14];
    const float* Wo  = (const float*)d_in[15];
    const float* bo  = (const float*)d_in[16];
    const float* Weo = (const float*)d_in[17];
    const float* beo = (const float*)d_in[18];
    float* out = (float*)d_out;

    void *qp, *kp, *vp;
    cudaGetSymbolAddress(&qp, g_qh);
    cudaGetSymbolAddress(&kp, g_kh);
    cudaGetSymbolAddress(&vp, g_vh);

    mask_kernel<<<BSZ, 256>>>(mask_raw);

    // QKV: Q/K compacted, V full — one launch
    qkv_kernel<<<1152, 256>>>(
        nodes, edges, Wq, Wk, Wv, bq, bk, bv,
        Weq, Wek, Wev, beq, bek, bev,
        (__half*)qp, (__half*)kp, (__half*)vp, SCALE * LOG2E);

    // Partial V sums per (b,h)
    vmean_kernel<<<BSZ * HEADS * NCH, 256>>>();

    // Flash attention + patch in idle CTAs
    cudaFuncSetAttribute(attn_f16_kernel,
                         cudaFuncAttributeMaxDynamicSharedMemorySize, ATTN_SMEM_BYTES);
    attn_f16_kernel<<<dim3(24, BSZ * HEADS), 256, ATTN_SMEM_BYTES>>>();

    // Both output projections in one launch
    outproj_kernel<<<160, 256>>>(Wo, bo, Weo, beo, out);
}

// round 14
// speedup vs baseline: 1.2622x; 1.0317x over previous
#include <cuda_runtime.h>
#include <cuda_fp16.h>
#include <float.h>
#include <math.h>
#include <stdint.h>

// Problem constants
#define BSZ   2
#define NN    1024
#define EE    2048
#define LTOT  3072
#define DIMN  128
#define EDIM  256
#define HEADS 8
#define DHEAD 64
#define INNER 512
#define SCALE 0.125f
#define LOG2E 1.4426950408889634f
#define VCH   24                                // vmean chunks per (b,h): 8 node + 16 edge

// Scratch (fp16 intermediates)
__device__ __half g_qh[BSZ * HEADS * LTOT * DHEAD];   // COMPACTED rows, pre-scaled
__device__ __half g_kh[BSZ * HEADS * LTOT * DHEAD];   // COMPACTED rows
__device__ __half g_vh[BSZ * HEADS * LTOT * DHEAD];   // full (all rows)
__device__ __half g_oh[BSZ * LTOT * INNER];
__device__ int    g_mask[BSZ * LTOT];
__device__ int    g_kidx[BSZ * LTOT];                 // compacted unmasked indices
__device__ int    g_nk[BSZ];                          // total unmasked
__device__ int    g_nn[BSZ];                          // unmasked among nodes
__device__ float  g_vpart[BSZ * HEADS * VCH * DHEAD]; // partial V sums (fp32, pre-round)

// ---------------------------------------------------------------------------
// PTX helpers
// ---------------------------------------------------------------------------
__device__ __forceinline__ uint32_t sptr(const void* p) {
    return (uint32_t)__cvta_generic_to_shared(p);
}
__device__ __forceinline__ void ldsm_x4(uint32_t& r0, uint32_t& r1,
                                        uint32_t& r2, uint32_t& r3, uint32_t addr) {
    asm volatile("ldmatrix.sync.aligned.m8n8.x4.shared.b16 {%0,%1,%2,%3}, [%4];"
                 : "=r"(r0), "=r"(r1), "=r"(r2), "=r"(r3) : "r"(addr));
}
__device__ __forceinline__ void ldsm_x4_t(uint32_t& r0, uint32_t& r1,
                                          uint32_t& r2, uint32_t& r3, uint32_t addr) {
    asm volatile("ldmatrix.sync.aligned.m8n8.x4.trans.shared.b16 {%0,%1,%2,%3}, [%4];"
                 : "=r"(r0), "=r"(r1), "=r"(r2), "=r"(r3) : "r"(addr));
}
__device__ __forceinline__ void mma_f16(float c[4],
                                        uint32_t a0, uint32_t a1, uint32_t a2, uint32_t a3,
                                        uint32_t b0, uint32_t b1) {
    asm volatile(
        "mma.sync.aligned.m16n8k16.row.col.f32.f16.f16.f32 "
        "{%0,%1,%2,%3}, {%4,%5,%6,%7}, {%8,%9}, {%0,%1,%2,%3};"
        : "+f"(c[0]), "+f"(c[1]), "+f"(c[2]), "+f"(c[3])
        : "r"(a0), "r"(a1), "r"(a2), "r"(a3), "r"(b0), "r"(b1));
}
__device__ __forceinline__ void cp16(uint32_t dst, const void* src) {
    asm volatile("cp.async.cg.shared.global [%0], [%1], 16;" :: "r"(dst), "l"(src));
}
__device__ __forceinline__ void cp_commit() {
    asm volatile("cp.async.commit_group;");
}
__device__ __forceinline__ void cp_wait0() {
    asm volatile("cp.async.wait_group 0;");
}
__device__ __forceinline__ uint32_t packh2(float x, float y) {
    __half2 h = __floats2half2_rn(x, y);
    return *reinterpret_cast<uint32_t*>(&h);
}
__device__ __forceinline__ float fexp2(float x) {
    float y;
    asm("ex2.approx.ftz.f32 %0, %1;" : "=f"(y) : "f"(x));
    return y;
}

// ---------------------------------------------------------------------------
// Mask decode + per-batch compaction (also counts node-region unmasked).
// ---------------------------------------------------------------------------
__global__ void mask_kernel(const unsigned char* __restrict__ raw) {
    __shared__ int partial[256];
    __shared__ int pfx[256];
    __shared__ int pnode[256];
    const int n = BSZ * LTOT;
    const int b = blockIdx.x;
    const int tid = threadIdx.x;

    int cnt = 0;
    for (int i = tid; i < n; i += 256) cnt += (raw[i] != 0);
    partial[tid] = cnt;
    __syncthreads();
    for (int s = 128; s > 0; s >>= 1) {
        if (tid < s) partial[tid] += partial[tid + s];
        __syncthreads();
    }
    const int width1 = partial[0] > (n * 3 / 8);
    const int* raw32 = (const int*)raw;

    int bits[12];
    int myc = 0, mync = 0;
    #pragma unroll
    for (int i = 0; i < 12; i++) {
        int li = tid * 12 + i;
        int gi = b * LTOT + li;
        int v = width1 ? (raw[gi] != 0) : (raw32[gi] != 0);
        g_mask[gi] = v;
        bits[i] = v;
        myc += v;
        if (li < NN) mync += v;
    }
    pfx[tid] = myc;
    pnode[tid] = mync;
    __syncthreads();
    for (int s = 128; s > 0; s >>= 1) {
        if (tid < s) pnode[tid] += pnode[tid + s];
        __syncthreads();
    }
    if (tid == 0) {
        g_nn[b] = pnode[0];
        int acc = 0;
        for (int t = 0; t < 256; t++) { int c = pfx[t]; pfx[t] = acc; acc += c; }
        g_nk[b] = acc;
    }
    __syncthreads();
    int off = b * LTOT + pfx[tid];
    #pragma unroll
    for (int i = 0; i < 12; i++)
        if (bits[i]) g_kidx[off++] = tid * 12 + i;
}

// ---------------------------------------------------------------------------
// Dense GEMM body. VSUM=true (V projection): additionally reduces this CTA's
// 128 rows of biased fp32 outputs into g_vpart[(b,h,chunk)] — the CTA covers
// exactly one head's 64 dims (col tile == head) and 128 rows of one batch.
// ---------------------------------------------------------------------------
template <bool AHALF, int DSTMODE, bool VSUM>
__device__ __forceinline__ void gemm_body(
        const void* __restrict__ Ap, const float* __restrict__ W,
        const float* __restrict__ bias, void* __restrict__ dst, float scl,
        int K, int Ncols, int rowsPerBatch, int aBatchStride, int aSeqOff,
        int dstSeqOff, int row0, int col0, int chunkOff) {
    __shared__ __align__(16) __half sA[128 * 40];
    __shared__ __align__(16) __half sW[32 * 72];

    const int tid = threadIdx.x;
    const int warp = tid >> 5, lane = tid & 31;
    const int g = lane >> 2, qd = lane & 3;
    const int wy = warp >> 1, wx = warp & 1;

    const uint32_t uA = sptr(sA);
    const uint32_t uW = sptr(sW);
    const int offA = ((lane & 7) + ((lane >> 3) & 1) * 8) * 80 + (lane >> 4) * 16;
    const int offW = ((lane & 7) + ((lane >> 3) & 1) * 8) * 144 + (lane >> 4) * 16;

    float acc[2][4][4] = {};

    for (int kt = 0; kt < K; kt += 32) {
        #pragma unroll
        for (int t = 0; t < 8; t++) {
            int idx = tid + t * 256;
            int i = idx >> 4, k2 = idx & 15;
            int m = row0 + i;
            int bb = m / rowsPerBatch;
            int r = m - bb * rowsPerBatch;
            size_t arow = (size_t)(bb * aBatchStride + aSeqOff + r) * K + kt + 2 * k2;
            if (AHALF) {
                ((__half2*)sA)[i * 20 + k2] = *(const __half2*)((const __half*)Ap + arow);
            } else {
                float2 v = *(const float2*)((const float*)Ap + arow);
                ((__half2*)sA)[i * 20 + k2] = __floats2half2_rn(v.x, v.y);
            }
        }
        #pragma unroll
        for (int t = 0; t < 4; t++) {
            int idx = tid + t * 256;
            int kr = idx >> 5, n2 = idx & 31;
            float2 v = *(const float2*)&W[(size_t)(kt + kr) * Ncols + col0 + 2 * n2];
            ((__half2*)sW)[kr * 36 + n2] = __floats2half2_rn(v.x, v.y);
        }
        __syncthreads();

        #pragma unroll
        for (int kk = 0; kk < 2; kk++) {
            uint32_t a[2][4];
            #pragma unroll
            for (int mt = 0; mt < 2; mt++)
                ldsm_x4(a[mt][0], a[mt][1], a[mt][2], a[mt][3],
                        uA + (wy * 32 + mt * 16) * 80 + kk * 32 + offA);
            #pragma unroll
            for (int p = 0; p < 2; p++) {
                uint32_t b0, b1, b2, b3;
                ldsm_x4_t(b0, b1, b2, b3,
                          uW + kk * 16 * 144 + (wx * 32 + p * 16) * 2 + offW);
                mma_f16(acc[0][2 * p],     a[0][0], a[0][1], a[0][2], a[0][3], b0, b1);
                mma_f16(acc[0][2 * p + 1], a[0][0], a[0][1], a[0][2], a[0][3], b2, b3);
                mma_f16(acc[1][2 * p],     a[1][0], a[1][1], a[1][2], a[1][3], b0, b1);
                mma_f16(acc[1][2 * p + 1], a[1][0], a[1][1], a[1][2], a[1][3], b2, b3);
            }
        }
        __syncthreads();
    }

    float vsum[4][2];
    if (VSUM) {
        #pragma unroll
        for (int n = 0; n < 4; n++) { vsum[n][0] = 0.f; vsum[n][1] = 0.f; }
    }

    #pragma unroll
    for (int mt = 0; mt < 2; mt++) {
        #pragma unroll
        for (int hh = 0; hh < 2; hh++) {
            int m = row0 + wy * 32 + mt * 16 + g + 8 * hh;
            int bb = m / rowsPerBatch;
            int r = m - bb * rowsPerBatch;
            #pragma unroll
            for (int n = 0; n < 4; n++) {
                int c = col0 + wx * 32 + n * 8 + 2 * qd;
                float v0 = (acc[mt][n][hh * 2 + 0] + bias[c]) * scl;
                float v1 = (acc[mt][n][hh * 2 + 1] + bias[c + 1]) * scl;
                if (VSUM) { vsum[n][0] += v0; vsum[n][1] += v1; }
                if (DSTMODE == 0) {
                    int hidx = c >> 6, d = c & 63;
                    __half* dh = (__half*)dst;
                    *(__half2*)&dh[((size_t)(bb * HEADS + hidx) * LTOT +
                                    dstSeqOff + r) * DHEAD + d] = __floats2half2_rn(v0, v1);
                } else {
                    float* df = (float*)dst;
                    *(float2*)&df[(size_t)m * Ncols + c] = make_float2(v0, v1);
                }
            }
        }
    }

    if (VSUM) {
        // Reduce over the 8 g-lanes (32 rows per warp summed)
        #pragma unroll
        for (int n = 0; n < 4; n++)
            #pragma unroll
            for (int e = 0; e < 2; e++) {
                float x = vsum[n][e];
                x += __shfl_xor_sync(0xffffffffu, x, 4);
                x += __shfl_xor_sync(0xffffffffu, x, 8);
                x += __shfl_xor_sync(0xffffffffu, x, 16);
                vsum[n][e] = x;
            }
        float* vs = (float*)sA;                  // 256 floats; sA is dead here
        if (g == 0) {
            #pragma unroll
            for (int n = 0; n < 4; n++) {
                vs[wy * 64 + wx * 32 + n * 8 + 2 * qd + 0] = vsum[n][0];
                vs[wy * 64 + wx * 32 + n * 8 + 2 * qd + 1] = vsum[n][1];
            }
        }
        __syncthreads();
        if (tid < DHEAD) {
            float s = vs[tid] + vs[64 + tid] + vs[128 + tid] + vs[192 + tid];
            int bb = row0 / rowsPerBatch;
            int h = col0 >> 6;
            int chunk = (row0 - bb * rowsPerBatch) / 128 + chunkOff;
            g_vpart[((size_t)(bb * HEADS + h) * VCH + chunk) * DHEAD + tid] = s;
        }
    }
}

// ---------------------------------------------------------------------------
// Compacted-row GEMM for Q/K projections (unchanged from R13).
// ---------------------------------------------------------------------------
__device__ __forceinline__ void gemm_qk_compact(
        const float* __restrict__ A,
        const float* __restrict__ W, const float* __restrict__ bias,
        __half* __restrict__ dst, float scl, int K, int srcOff,
        const int* __restrict__ kidx,
        int slot0, int segEnd, int bhBase, int col0) {
    __shared__ __align__(16) __half sA[128 * 40];
    __shared__ __align__(16) __half sW[32 * 72];

    const int tid = threadIdx.x;
    const int warp = tid >> 5, lane = tid & 31;
    const int g = lane >> 2, qd = lane & 3;
    const int wy = warp >> 1, wx = warp & 1;

    const uint32_t uA = sptr(sA);
    const uint32_t uW = sptr(sW);
    const int offA = ((lane & 7) + ((lane >> 3) & 1) * 8) * 80 + (lane >> 4) * 16;
    const int offW = ((lane & 7) + ((lane >> 3) & 1) * 8) * 144 + (lane >> 4) * 16;

    float acc[2][4][4] = {};

    for (int kt = 0; kt < K; kt += 32) {
        #pragma unroll
        for (int t = 0; t < 8; t++) {
            int idx = tid + t * 256;
            int i = idx >> 4, k2 = idx & 15;
            int slot = slot0 + i;
            int src = (slot < segEnd) ? (kidx[slot] - srcOff) : 0;
            float2 v = *(const float2*)&A[(size_t)src * K + kt + 2 * k2];
            ((__half2*)sA)[i * 20 + k2] = __floats2half2_rn(v.x, v.y);
        }
        #pragma unroll
        for (int t = 0; t < 4; t++) {
            int idx = tid + t * 256;
            int kr = idx >> 5, n2 = idx & 31;
            float2 v = *(const float2*)&W[(size_t)(kt + kr) * INNER + col0 + 2 * n2];
            ((__half2*)sW)[kr * 36 + n2] = __floats2half2_rn(v.x, v.y);
        }
        __syncthreads();

        #pragma unroll
        for (int kk = 0; kk < 2; kk++) {
            uint32_t a[2][4];
            #pragma unroll
            for (int mt = 0; mt < 2; mt++)
                ldsm_x4(a[mt][0], a[mt][1], a[mt][2], a[mt][3],
                        uA + (wy * 32 + mt * 16) * 80 + kk * 32 + offA);
            #pragma unroll
            for (int p = 0; p < 2; p++) {
                uint32_t b0, b1, b2, b3;
                ldsm_x4_t(b0, b1, b2, b3,
                          uW + kk * 16 * 144 + (wx * 32 + p * 16) * 2 + offW);
                mma_f16(acc[0][2 * p],     a[0][0], a[0][1], a[0][2], a[0][3], b0, b1);
                mma_f16(acc[0][2 * p + 1], a[0][0], a[0][1], a[0][2], a[0][3], b2, b3);
                mma_f16(acc[1][2 * p],     a[1][0], a[1][1], a[1][2], a[1][3], b0, b1);
                mma_f16(acc[1][2 * p + 1], a[1][0], a[1][1], a[1][2], a[1][3], b2, b3);
            }
        }
        __syncthreads();
    }

    #pragma unroll
    for (int mt = 0; mt < 2; mt++) {
        #pragma unroll
        for (int hh = 0; hh < 2; hh++) {
            int slot = slot0 + wy * 32 + mt * 16 + g + 8 * hh;
            bool ok = slot < segEnd;
            #pragma unroll
            for (int n = 0; n < 4; n++) {
                int c = col0 + wx * 32 + n * 8 + 2 * qd;
                float v0 = (acc[mt][n][hh * 2 + 0] + bias[c]) * scl;
                float v1 = (acc[mt][n][hh * 2 + 1] + bias[c + 1]) * scl;
                if (ok) {
                    int hidx = c >> 6, d = c & 63;
                    *(__half2*)&dst[((size_t)(bhBase + hidx) * LTOT + slot) * DHEAD + d] =
                        __floats2half2_rn(v0, v1);
                }
            }
        }
    }
}

// ---------------------------------------------------------------------------
// Fused QKV projections: Q/K compacted, V dense (+fused vpart reduction).
// 1152 CTAs: [0,256) node Q/K, [256,768) edge Q/K, [768,1152) V dense.
// ---------------------------------------------------------------------------
__global__ __launch_bounds__(256) void qkv_kernel(
        const float* __restrict__ nodes, const float* __restrict__ edges,
        const float* Wq, const float* Wk, const float* Wv,
        const float* bq, const float* bk, const float* bv,
        const float* Weq, const float* Wek, const float* Wev,
        const float* beq, const float* bek, const float* bev,
        __half* qp, __half* kp, __half* vp, float qscale) {
    const int t = blockIdx.x;
    if (t < 256) {
        const int pr = t >> 7;
        const int rem = t & 127;
        const int b = rem >> 6;
        const int rt = (rem >> 3) & 7;
        const int ct = rem & 7;
        const int nn = g_nn[b];
        const int slot0 = rt * 128;
        if (slot0 >= nn) return;
        gemm_qk_compact(nodes + (size_t)b * NN * DIMN,
                        pr ? Wk : Wq, pr ? bk : bq, pr ? kp : qp,
                        pr ? 1.f : qscale, DIMN, 0,
                        g_kidx + b * LTOT, slot0, nn, b * HEADS, ct * 64);
    } else if (t < 768) {
        const int u = t - 256;
        const int pr = u >> 8;
        const int rem = u & 255;
        const int b = rem >> 7;
        const int rt = (rem >> 3) & 15;
        const int ct = rem & 7;
        const int nn = g_nn[b];
        const int nk = g_nk[b];
        const int slot0 = nn + rt * 128;
        if (slot0 >= nk) return;
        gemm_qk_compact(edges + (size_t)b * EE * EDIM,
                        pr ? Wek : Weq, pr ? bek : beq, pr ? kp : qp,
                        pr ? 1.f : qscale, EDIM, NN,
                        g_kidx + b * LTOT, slot0, nk, b * HEADS, ct * 64);
    } else {
        const int u = t - 768;
        if (u < 128) {
            const int row0 = (u >> 3) * 128, col0 = (u & 7) * 64;
            gemm_body<false, 0, true>(nodes, Wv, bv, vp, 1.f,
                                      128, 512, 1024, 1024, 0, 0, row0, col0, 0);
        } else {
            const int v = u - 128;
            const int row0 = (v >> 3) * 128, col0 = (v & 7) * 64;
            gemm_body<false, 0, true>(edges, Wev, bev, vp, 1.f,
                                      256, 512, 2048, 2048, 0, 1024, row0, col0, 8);
        }
    }
}

// ---------------------------------------------------------------------------
// Fused output projections (node + edge) in one launch. 160 CTAs.
// ---------------------------------------------------------------------------
__global__ __launch_bounds__(256) void outproj_kernel(
        const float* __restrict__ Wo, const float* __restrict__ bo,
        const float* __restrict__ Weo, const float* __restrict__ beo,
        float* __restrict__ out) {
    const int t = blockIdx.x;
    if (t < 32) {
        const int col0 = (t & 1) * 64, row0 = (t >> 1) * 128;
        gemm_body<true, 1, false>(g_oh, Wo, bo, out, 1.f,
                                  512, 128, 1024, 3072, 0, 0, row0, col0, 0);
    } else {
        const int u = t - 32;
        const int col0 = (u & 3) * 64, row0 = (u >> 2) * 128;
        gemm_body<true, 1, false>(g_oh, Weo, beo, out + 2 * 1024 * 128, 1.f,
                                  512, 256, 2048, 3072, 1024, 0, row0, col0, 0);
    }
}

// ---------------------------------------------------------------------------
// Flash attention over compacted rows (R13 form). Idle CTAs patch masked
// rows of g_oh from g_vpart (uniform softmax = Vmean).
// ---------------------------------------------------------------------------
#define KVSTR 72
#define KVBUF_H (64 * KVSTR)
#define KVBUF_B (KVBUF_H * 2)
#define ATTN_SMEM_BYTES (4 * KVBUF_B)

__device__ __forceinline__ void patch_tiles(int b, int h, int bh, int pstart, int pstep) {
    __shared__ float vms[64];
    const int tid = threadIdx.x;
    if (tid < 64) {
        float s = 0.f;
        #pragma unroll
        for (int c = 0; c < VCH; c++)
            s += g_vpart[((size_t)bh * VCH + c) * DHEAD + tid];
        vms[tid] = s * (1.0f / LTOT);
    }
    __syncthreads();
    const int dg = tid & 7;
    uint4 hv;
    hv.x = packh2(vms[dg * 8 + 0], vms[dg * 8 + 1]);
    hv.y = packh2(vms[dg * 8 + 2], vms[dg * 8 + 3]);
    hv.z = packh2(vms[dg * 8 + 4], vms[dg * 8 + 5]);
    hv.w = packh2(vms[dg * 8 + 6], vms[dg * 8 + 7]);
    for (int p = pstart; p < 24; p += pstep) {
        #pragma unroll
        for (int pass = 0; pass < 4; pass++) {
            int r = p * 128 + pass * 32 + (tid >> 3);
            if (!g_mask[b * LTOT + r])
                *(uint4*)&g_oh[(size_t)(b * LTOT + r) * INNER + h * DHEAD + dg * 8] = hv;
        }
    }
}

__global__ __launch_bounds__(256, 2) void attn_f16_kernel() {
    const int bh = blockIdx.y;
    const int b = bh >> 3, h = bh & 7;
    const int nk = g_nk[b];
    const int q0 = blockIdx.x * 128;
    const int qtiles = (nk + 127) >> 7;
    const int nidle = 24 - qtiles;

    if (q0 >= nk) {
        patch_tiles(b, h, bh, blockIdx.x - qtiles, nidle);
        return;
    }

    extern __shared__ __align__(16) char smraw[];
    __half* Kh = (__half*)smraw;                 // [2][64][72]
    __half* Vh = (__half*)(smraw + 2 * KVBUF_B); // [2][64][72]

    const int tid = threadIdx.x;
    const int warp = tid >> 5, lane = tid & 31;
    const int g = lane >> 2, qd = lane & 3;

    const __half* Qg = g_qh + (size_t)bh * LTOT * DHEAD;   // compacted
    const __half* Kg = g_kh + (size_t)bh * LTOT * DHEAD;   // compacted
    const __half* Vg = g_vh + (size_t)bh * LTOT * DHEAD;   // full
    const int* kidx = g_kidx + b * LTOT;
    const int NIT = (nk + 63) >> 6;

    const uint32_t uK = sptr(Kh), uV = sptr(Vh);
    const int offA = ((lane & 7) + ((lane >> 3) & 1) * 8) * 144 + (lane >> 4) * 16;
    const int offK = ((lane & 7) + ((lane >> 4) & 1) * 8) * 144 + ((lane >> 3) & 1) * 16;

    const int prow = tid >> 3;                   // 0..31
    const int pch = (tid & 7) * 16;              // byte offset 0..112

    // Prologue: load tile 0 (K dense, V gathered)
    {
        #pragma unroll
        for (int rr = 0; rr < 2; rr++) {
            int r = prow + rr * 32;
            int kdrow = (r < nk) ? r : 0;
            int vrow = (r < nk) ? kidx[r] : 0;
            cp16(uK + r * 144 + pch, Kg + (size_t)kdrow * 64 + (pch >> 1));
            cp16(uV + r * 144 + pch, Vg + (size_t)vrow * 64 + (pch >> 1));
        }
        cp_commit();
    }

    // Query rows: dense compacted slots
    const int qr_a = q0 + warp * 16 + g;
    const int qr_b = qr_a + 8;
    const int valid0 = qr_a < nk;
    const int valid1 = qr_b < nk;

    uint32_t qa[4][4];
    {
        const __half* qr0p = Qg + (size_t)(valid0 ? qr_a : 0) * DHEAD;
        const __half* qr1p = Qg + (size_t)(valid1 ? qr_b : 0) * DHEAD;
        #pragma unroll
        for (int kk = 0; kk < 4; kk++) {
            int c = kk * 16 + 2 * qd;
            qa[kk][0] = *(const uint32_t*)(qr0p + c);
            qa[kk][1] = *(const uint32_t*)(qr1p + c);
            qa[kk][2] = *(const uint32_t*)(qr0p + c + 8);
            qa[kk][3] = *(const uint32_t*)(qr1p + c + 8);
        }
    }

    float m_i[2] = {-FLT_MAX, -FLT_MAX};
    float l_i[2] = {0.f, 0.f};
    float o[8][4] = {};

    for (int it = 0; it < NIT; it++) {
        const int bf = it & 1;
        const int k0 = it * 64;
        cp_wait0();
        __syncthreads();

        if (it + 1 < NIT) {
            uint32_t uKn = uK + (bf ^ 1) * KVBUF_B;
            uint32_t uVn = uV + (bf ^ 1) * KVBUF_B;
            #pragma unroll
            for (int rr = 0; rr < 2; rr++) {
                int r = prow + rr * 32;
                int gi = k0 + 64 + r;
                int kdrow = (gi < nk) ? gi : 0;
                int vrow = (gi < nk) ? kidx[gi] : 0;
                cp16(uKn + r * 144 + pch, Kg + (size_t)kdrow * 64 + (pch >> 1));
                cp16(uVn + r * 144 + pch, Vg + (size_t)vrow * 64 + (pch >> 1));
            }
            cp_commit();
        }

        const uint32_t uKb = uK + bf * KVBUF_B;
        const uint32_t uVb = uV + bf * KVBUF_B;

        // ---- S = Q @ K^T ----
        float s[8][4] = {};
        #pragma unroll
        for (int kk = 0; kk < 4; kk++) {
            #pragma unroll
            for (int p = 0; p < 4; p++) {
                uint32_t b0, b1, b2, b3;
                ldsm_x4(b0, b1, b2, b3, uKb + p * 16 * 144 + kk * 32 + offK);
                mma_f16(s[2 * p],     qa[kk][0], qa[kk][1], qa[kk][2], qa[kk][3], b0, b1);
                mma_f16(s[2 * p + 1], qa[kk][0], qa[kk][1], qa[kk][2], qa[kk][3], b2, b3);
            }
        }

        // ---- tail masking (key side) ----
        if (k0 + 64 > nk) {
            #pragma unroll
            for (int nt = 0; nt < 8; nt++) {
                int j0 = k0 + nt * 8 + 2 * qd;
                if (j0 >= nk)     { s[nt][0] = -FLT_MAX; s[nt][2] = -FLT_MAX; }
                if (j0 + 1 >= nk) { s[nt][1] = -FLT_MAX; s[nt][3] = -FLT_MAX; }
            }
        }

        // ---- online softmax (base-2) ----
        #pragma unroll
        for (int hh = 0; hh < 2; hh++) {
            float mx = -FLT_MAX;
            #pragma unroll
            for (int nt = 0; nt < 8; nt++)
                mx = fmaxf(mx, fmaxf(s[nt][hh * 2], s[nt][hh * 2 + 1]));
            mx = fmaxf(mx, __shfl_xor_sync(0xffffffffu, mx, 1));
            mx = fmaxf(mx, __shfl_xor_sync(0xffffffffu, mx, 2));
            float mnew = fmaxf(m_i[hh], mx);
            float corr = fexp2(m_i[hh] - mnew);
            m_i[hh] = mnew;
            float rs = 0.f;
            #pragma unroll
            for (int nt = 0; nt < 8; nt++) {
                float p0 = fexp2(s[nt][hh * 2]     - mnew);
                float p1 = fexp2(s[nt][hh * 2 + 1] - mnew);
                rs += p0 + p1;
                s[nt][hh * 2]     = p0;
                s[nt][hh * 2 + 1] = p1;
            }
            rs += __shfl_xor_sync(0xffffffffu, rs, 1);
            rs += __shfl_xor_sync(0xffffffffu, rs, 2);
            l_i[hh] = l_i[hh] * corr + rs;
            #pragma unroll
            for (int nt = 0; nt < 8; nt++) {
                o[nt][hh * 2]     *= corr;
                o[nt][hh * 2 + 1] *= corr;
            }
        }

        // ---- O += P @ V ----
        #pragma unroll
        for (int jj = 0; jj < 4; jj++) {
            uint32_t pa0 = packh2(s[2 * jj][0],     s[2 * jj][1]);
            uint32_t pa1 = packh2(s[2 * jj][2],     s[2 * jj][3]);
            uint32_t pa2 = packh2(s[2 * jj + 1][0], s[2 * jj + 1][1]);
            uint32_t pa3 = packh2(s[2 * jj + 1][2], s[2 * jj + 1][3]);
            #pragma unroll
            for (int p = 0; p < 4; p++) {
                uint32_t b0, b1, b2, b3;
                ldsm_x4_t(b0, b1, b2, b3, uVb + jj * 16 * 144 + p * 32 + offA);
                mma_f16(o[2 * p],     pa0, pa1, pa2, pa3, b0, b1);
                mma_f16(o[2 * p + 1], pa0, pa1, pa2, pa3, b2, b3);
            }
        }
    }

    // ---- epilogue: normalize + scatter to original row indices ----
    #pragma unroll
    for (int hh = 0; hh < 2; hh++) {
        if (!(hh ? valid1 : valid0)) continue;
        const int qrow = kidx[hh ? qr_b : qr_a];
        float inv = 1.f / l_i[hh];
        __half* dstp = &g_oh[(size_t)(b * LTOT + qrow) * INNER + h * DHEAD];
        #pragma unroll
        for (int nt = 0; nt < 8; nt++) {
            int d0 = nt * 8 + 2 * qd;
            *(__half2*)&dstp[d0] =
                __floats2half2_rn(o[nt][hh * 2] * inv, o[nt][hh * 2 + 1] * inv);
        }
    }

    // Fallback: if no idle CTAs exist (nk > 2944), last CTA patches everything.
    if (nidle == 0 && blockIdx.x == 23) {
        __syncthreads();
        patch_tiles(b, h, bh, 0, 1);
    }
}

// ---------------------------------------------------------------------------
// kernel_launch
// ---------------------------------------------------------------------------
extern "C" void kernel_launch(void* const* d_in, const int* in_sizes, int n_in,
                              void* d_out, int out_size) {
    const float* nodes = (const float*)d_in[0];
    const float* edges = (const float*)d_in[1];
    const unsigned char* mask_raw = (const unsigned char*)d_in[2];
    const float* Wq  = (const float*)d_in[3];
    const float* bq  = (const float*)d_in[4];
    const float* Wk  = (const float*)d_in[5];
    const float* bk  = (const float*)d_in[6];
    const float* Wv  = (const float*)d_in[7];
    const float* bv  = (const float*)d_in[8];
    const float* Weq = (const float*)d_in[9];
    const float* beq = (const float*)d_in[10];
    const float* Wek = (const float*)d_in[11];
    const float* bek = (const float*)d_in[12];
    const float* Wev = (const float*)d_in[13];
    const float* bev = (const float*)d_in[14];
    const float* Wo  = (const float*)d_in[15];
    const float* bo  = (const float*)d_in[16];
    const float* Weo = (const float*)d_in[17];
    const float* beo = (const float*)d_in[18];
    float* out = (float*)d_out;

    void *qp, *kp, *vp;
    cudaGetSymbolAddress(&qp, g_qh);
    cudaGetSymbolAddress(&kp, g_kh);
    cudaGetSymbolAddress(&vp, g_vh);

    mask_kernel<<<BSZ, 256>>>(mask_raw);

    // QKV: Q/K compacted, V full with fused vpart reduction — one launch
    qkv_kernel<<<1152, 256>>>(
        nodes, edges, Wq, Wk, Wv, bq, bk, bv,
        Weq, Wek, Wev, beq, bek, bev,
        (__half*)qp, (__half*)kp, (__half*)vp, SCALE * LOG2E);

    // Flash attention + patch in idle CTAs
    cudaFuncSetAttribute(attn_f16_kernel,
                         cudaFuncAttributeMaxDynamicSharedMemorySize, ATTN_SMEM_BYTES);
    attn_f16_kernel<<<dim3(24, BSZ * HEADS), 256, ATTN_SMEM_BYTES>>>();

    // Both output projections in one launch
    outproj_kernel<<<160, 256>>>(Wo, bo, Weo, beo, out);
}

// round 15
// speedup vs baseline: 1.3046x; 1.0336x over previous
#include <cuda_runtime.h>
#include <cuda_fp16.h>
#include <float.h>
#include <math.h>
#include <stdint.h>

// Problem constants
#define BSZ   2
#define NN    1024
#define EE    2048
#define LTOT  3072
#define DIMN  128
#define EDIM  256
#define HEADS 8
#define DHEAD 64
#define INNER 512
#define SCALE 0.125f
#define LOG2E 1.4426950408889634f
#define VCH   24                                // vmean chunks per (b,h): 8 node + 16 edge

// Scratch (fp16 intermediates)
__device__ __half g_qh[BSZ * HEADS * LTOT * DHEAD];   // COMPACTED rows, pre-scaled
__device__ __half g_kh[BSZ * HEADS * LTOT * DHEAD];   // COMPACTED rows
__device__ __half g_vh[BSZ * HEADS * LTOT * DHEAD];   // full (all rows)
__device__ __half g_oh[BSZ * LTOT * INNER];
__device__ int    g_mask[BSZ * LTOT];
__device__ int    g_kidx[BSZ * LTOT];                 // compacted unmasked indices
__device__ int    g_nk[BSZ];                          // total unmasked
__device__ int    g_nn[BSZ];                          // unmasked among nodes
__device__ float  g_vpart[BSZ * HEADS * VCH * DHEAD]; // partial V sums (fp32, pre-round)

// ---------------------------------------------------------------------------
// PTX helpers
// ---------------------------------------------------------------------------
__device__ __forceinline__ uint32_t sptr(const void* p) {
    return (uint32_t)__cvta_generic_to_shared(p);
}
__device__ __forceinline__ void ldsm_x4(uint32_t& r0, uint32_t& r1,
                                        uint32_t& r2, uint32_t& r3, uint32_t addr) {
    asm volatile("ldmatrix.sync.aligned.m8n8.x4.shared.b16 {%0,%1,%2,%3}, [%4];"
                 : "=r"(r0), "=r"(r1), "=r"(r2), "=r"(r3) : "r"(addr));
}
__device__ __forceinline__ void ldsm_x4_t(uint32_t& r0, uint32_t& r1,
                                          uint32_t& r2, uint32_t& r3, uint32_t addr) {
    asm volatile("ldmatrix.sync.aligned.m8n8.x4.trans.shared.b16 {%0,%1,%2,%3}, [%4];"
                 : "=r"(r0), "=r"(r1), "=r"(r2), "=r"(r3) : "r"(addr));
}
__device__ __forceinline__ void mma_f16(float c[4],
                                        uint32_t a0, uint32_t a1, uint32_t a2, uint32_t a3,
                                        uint32_t b0, uint32_t b1) {
    asm volatile(
        "mma.sync.aligned.m16n8k16.row.col.f32.f16.f16.f32 "
        "{%0,%1,%2,%3}, {%4,%5,%6,%7}, {%8,%9}, {%0,%1,%2,%3};"
        : "+f"(c[0]), "+f"(c[1]), "+f"(c[2]), "+f"(c[3])
        : "r"(a0), "r"(a1), "r"(a2), "r"(a3), "r"(b0), "r"(b1));
}
__device__ __forceinline__ void cp16(uint32_t dst, const void* src) {
    asm volatile("cp.async.cg.shared.global [%0], [%1], 16;" :: "r"(dst), "l"(src));
}
__device__ __forceinline__ void cp_commit() {
    asm volatile("cp.async.commit_group;");
}
__device__ __forceinline__ void cp_wait0() {
    asm volatile("cp.async.wait_group 0;");
}
__device__ __forceinline__ uint32_t packh2(float x, float y) {
    __half2 h = __floats2half2_rn(x, y);
    return *reinterpret_cast<uint32_t*>(&h);
}
__device__ __forceinline__ float fexp2(float x) {
    float y;
    asm("ex2.approx.ftz.f32 %0, %1;" : "=f"(y) : "f"(x));
    return y;
}

// ---------------------------------------------------------------------------
// Mask decode + per-batch compaction (also counts node-region unmasked).
// ---------------------------------------------------------------------------
__global__ void mask_kernel(const unsigned char* __restrict__ raw) {
    __shared__ int partial[256];
    __shared__ int pfx[256];
    __shared__ int pnode[256];
    const int n = BSZ * LTOT;
    const int b = blockIdx.x;
    const int tid = threadIdx.x;

    int cnt = 0;
    for (int i = tid; i < n; i += 256) cnt += (raw[i] != 0);
    partial[tid] = cnt;
    __syncthreads();
    for (int s = 128; s > 0; s >>= 1) {
        if (tid < s) partial[tid] += partial[tid + s];
        __syncthreads();
    }
    const int width1 = partial[0] > (n * 3 / 8);
    const int* raw32 = (const int*)raw;

    int bits[12];
    int myc = 0, mync = 0;
    #pragma unroll
    for (int i = 0; i < 12; i++) {
        int li = tid * 12 + i;
        int gi = b * LTOT + li;
        int v = width1 ? (raw[gi] != 0) : (raw32[gi] != 0);
        g_mask[gi] = v;
        bits[i] = v;
        myc += v;
        if (li < NN) mync += v;
    }
    pfx[tid] = myc;
    pnode[tid] = mync;
    __syncthreads();
    for (int s = 128; s > 0; s >>= 1) {
        if (tid < s) pnode[tid] += pnode[tid + s];
        __syncthreads();
    }
    if (tid == 0) {
        g_nn[b] = pnode[0];
        int acc = 0;
        for (int t = 0; t < 256; t++) { int c = pfx[t]; pfx[t] = acc; acc += c; }
        g_nk[b] = acc;
    }
    __syncthreads();
    int off = b * LTOT + pfx[tid];
    #pragma unroll
    for (int i = 0; i < 12; i++)
        if (bits[i]) g_kidx[off++] = tid * 12 + i;
}

// ---------------------------------------------------------------------------
// Dense GEMM body, register-double-buffered mainloop.
// VSUM=true (V projection): fused per-CTA row reduction to g_vpart.
// ---------------------------------------------------------------------------
template <bool AHALF, int DSTMODE, bool VSUM>
__device__ __forceinline__ void gemm_body(
        const void* __restrict__ Ap, const float* __restrict__ W,
        const float* __restrict__ bias, void* __restrict__ dst, float scl,
        int K, int Ncols, int rowsPerBatch, int aBatchStride, int aSeqOff,
        int dstSeqOff, int row0, int col0, int chunkOff) {
    __shared__ __align__(16) __half sA[128 * 40];
    __shared__ __align__(16) __half sW[32 * 72];

    const int tid = threadIdx.x;
    const int warp = tid >> 5, lane = tid & 31;
    const int g = lane >> 2, qd = lane & 3;
    const int wy = warp >> 1, wx = warp & 1;

    const uint32_t uA = sptr(sA);
    const uint32_t uW = sptr(sW);
    const int offA = ((lane & 7) + ((lane >> 3) & 1) * 8) * 80 + (lane >> 4) * 16;
    const int offW = ((lane & 7) + ((lane >> 3) & 1) * 8) * 144 + (lane >> 4) * 16;

    // Precompute per-thread A row pointers (8 chunks) and W row pointers (4)
    const float* aRowF[8];
    const __half* aRowH[8];
    #pragma unroll
    for (int t = 0; t < 8; t++) {
        int idx = tid + t * 256;
        int i = idx >> 4;
        int m = row0 + i;
        int bb = m / rowsPerBatch;
        int r = m - bb * rowsPerBatch;
        size_t base = (size_t)(bb * aBatchStride + aSeqOff + r) * K;
        if (AHALF) aRowH[t] = (const __half*)Ap + base;
        else       aRowF[t] = (const float*)Ap + base;
    }

    float2 raf[8];
    __half2 rah[8];
    float2 rw[4];

    // Preload k-tile 0
    #pragma unroll
    for (int t = 0; t < 8; t++) {
        int k2 = (tid + t * 256) & 15;
        if (AHALF) rah[t] = *(const __half2*)(aRowH[t] + 2 * k2);
        else       raf[t] = *(const float2*)(aRowF[t] + 2 * k2);
    }
    #pragma unroll
    for (int t = 0; t < 4; t++) {
        int idx = tid + t * 256;
        int kr = idx >> 5, n2 = idx & 31;
        rw[t] = *(const float2*)&W[(size_t)kr * Ncols + col0 + 2 * n2];
    }

    float acc[2][4][4] = {};

    for (int kt = 0; kt < K; kt += 32) {
        if (kt > 0) __syncthreads();   // previous mma done reading smem

        // Store staged regs -> smem (with conversion)
        #pragma unroll
        for (int t = 0; t < 8; t++) {
            int idx = tid + t * 256;
            int i = idx >> 4, k2 = idx & 15;
            ((__half2*)sA)[i * 20 + k2] =
                AHALF ? rah[t] : __floats2half2_rn(raf[t].x, raf[t].y);
        }
        #pragma unroll
        for (int t = 0; t < 4; t++) {
            int idx = tid + t * 256;
            int kr = idx >> 5, n2 = idx & 31;
            ((__half2*)sW)[kr * 36 + n2] = __floats2half2_rn(rw[t].x, rw[t].y);
        }

        // Issue loads for the next k-tile (consumed next iteration)
        if (kt + 32 < K) {
            #pragma unroll
            for (int t = 0; t < 8; t++) {
                int k2 = (tid + t * 256) & 15;
                if (AHALF) rah[t] = *(const __half2*)(aRowH[t] + kt + 32 + 2 * k2);
                else       raf[t] = *(const float2*)(aRowF[t] + kt + 32 + 2 * k2);
            }
            #pragma unroll
            for (int t = 0; t < 4; t++) {
                int idx = tid + t * 256;
                int kr = idx >> 5, n2 = idx & 31;
                rw[t] = *(const float2*)&W[(size_t)(kt + 32 + kr) * Ncols + col0 + 2 * n2];
            }
        }
        __syncthreads();

        #pragma unroll
        for (int kk = 0; kk < 2; kk++) {
            uint32_t a[2][4];
            #pragma unroll
            for (int mt = 0; mt < 2; mt++)
                ldsm_x4(a[mt][0], a[mt][1], a[mt][2], a[mt][3],
                        uA + (wy * 32 + mt * 16) * 80 + kk * 32 + offA);
            #pragma unroll
            for (int p = 0; p < 2; p++) {
                uint32_t b0, b1, b2, b3;
                ldsm_x4_t(b0, b1, b2, b3,
                          uW + kk * 16 * 144 + (wx * 32 + p * 16) * 2 + offW);
                mma_f16(acc[0][2 * p],     a[0][0], a[0][1], a[0][2], a[0][3], b0, b1);
                mma_f16(acc[0][2 * p + 1], a[0][0], a[0][1], a[0][2], a[0][3], b2, b3);
                mma_f16(acc[1][2 * p],     a[1][0], a[1][1], a[1][2], a[1][3], b0, b1);
                mma_f16(acc[1][2 * p + 1], a[1][0], a[1][1], a[1][2], a[1][3], b2, b3);
            }
        }
    }
    __syncthreads();   // before epilogue (VSUM reuses sA)

    float vsum[4][2];
    if (VSUM) {
        #pragma unroll
        for (int n = 0; n < 4; n++) { vsum[n][0] = 0.f; vsum[n][1] = 0.f; }
    }

    #pragma unroll
    for (int mt = 0; mt < 2; mt++) {
        #pragma unroll
        for (int hh = 0; hh < 2; hh++) {
            int m = row0 + wy * 32 + mt * 16 + g + 8 * hh;
            int bb = m / rowsPerBatch;
            int r = m - bb * rowsPerBatch;
            #pragma unroll
            for (int n = 0; n < 4; n++) {
                int c = col0 + wx * 32 + n * 8 + 2 * qd;
                float v0 = (acc[mt][n][hh * 2 + 0] + bias[c]) * scl;
                float v1 = (acc[mt][n][hh * 2 + 1] + bias[c + 1]) * scl;
                if (VSUM) { vsum[n][0] += v0; vsum[n][1] += v1; }
                if (DSTMODE == 0) {
                    int hidx = c >> 6, d = c & 63;
                    __half* dh = (__half*)dst;
                    *(__half2*)&dh[((size_t)(bb * HEADS + hidx) * LTOT +
                                    dstSeqOff + r) * DHEAD + d] = __floats2half2_rn(v0, v1);
                } else {
                    float* df = (float*)dst;
                    *(float2*)&df[(size_t)m * Ncols + c] = make_float2(v0, v1);
                }
            }
        }
    }

    if (VSUM) {
        #pragma unroll
        for (int n = 0; n < 4; n++)
            #pragma unroll
            for (int e = 0; e < 2; e++) {
                float x = vsum[n][e];
                x += __shfl_xor_sync(0xffffffffu, x, 4);
                x += __shfl_xor_sync(0xffffffffu, x, 8);
                x += __shfl_xor_sync(0xffffffffu, x, 16);
                vsum[n][e] = x;
            }
        float* vs = (float*)sA;                  // sA is dead here
        if (g == 0) {
            #pragma unroll
            for (int n = 0; n < 4; n++) {
                vs[wy * 64 + wx * 32 + n * 8 + 2 * qd + 0] = vsum[n][0];
                vs[wy * 64 + wx * 32 + n * 8 + 2 * qd + 1] = vsum[n][1];
            }
        }
        __syncthreads();
        if (tid < DHEAD) {
            float s = vs[tid] + vs[64 + tid] + vs[128 + tid] + vs[192 + tid];
            int bb = row0 / rowsPerBatch;
            int h = col0 >> 6;
            int chunk = (row0 - bb * rowsPerBatch) / 128 + chunkOff;
            g_vpart[((size_t)(bb * HEADS + h) * VCH + chunk) * DHEAD + tid] = s;
        }
    }
}

// ---------------------------------------------------------------------------
// Compacted-row GEMM for Q/K projections, register-double-buffered.
// ---------------------------------------------------------------------------
__device__ __forceinline__ void gemm_qk_compact(
        const float* __restrict__ A,
        const float* __restrict__ W, const float* __restrict__ bias,
        __half* __restrict__ dst, float scl, int K, int srcOff,
        const int* __restrict__ kidx,
        int slot0, int segEnd, int bhBase, int col0) {
    __shared__ __align__(16) __half sA[128 * 40];
    __shared__ __align__(16) __half sW[32 * 72];

    const int tid = threadIdx.x;
    const int warp = tid >> 5, lane = tid & 31;
    const int g = lane >> 2, qd = lane & 3;
    const int wy = warp >> 1, wx = warp & 1;

    const uint32_t uA = sptr(sA);
    const uint32_t uW = sptr(sW);
    const int offA = ((lane & 7) + ((lane >> 3) & 1) * 8) * 80 + (lane >> 4) * 16;
    const int offW = ((lane & 7) + ((lane >> 3) & 1) * 8) * 144 + (lane >> 4) * 16;

    const float* aRow[8];
    #pragma unroll
    for (int t = 0; t < 8; t++) {
        int idx = tid + t * 256;
        int slot = slot0 + (idx >> 4);
        int src = (slot < segEnd) ? (kidx[slot] - srcOff) : 0;
        aRow[t] = A + (size_t)src * K;
    }

    float2 ra[8];
    float2 rw[4];
    #pragma unroll
    for (int t = 0; t < 8; t++) {
        int k2 = (tid + t * 256) & 15;
        ra[t] = *(const float2*)(aRow[t] + 2 * k2);
    }
    #pragma unroll
    for (int t = 0; t < 4; t++) {
        int idx = tid + t * 256;
        int kr = idx >> 5, n2 = idx & 31;
        rw[t] = *(const float2*)&W[(size_t)kr * INNER + col0 + 2 * n2];
    }

    float acc[2][4][4] = {};

    for (int kt = 0; kt < K; kt += 32) {
        if (kt > 0) __syncthreads();

        #pragma unroll
        for (int t = 0; t < 8; t++) {
            int idx = tid + t * 256;
            int i = idx >> 4, k2 = idx & 15;
            ((__half2*)sA)[i * 20 + k2] = __floats2half2_rn(ra[t].x, ra[t].y);
        }
        #pragma unroll
        for (int t = 0; t < 4; t++) {
            int idx = tid + t * 256;
            int kr = idx >> 5, n2 = idx & 31;
            ((__half2*)sW)[kr * 36 + n2] = __floats2half2_rn(rw[t].x, rw[t].y);
        }

        if (kt + 32 < K) {
            #pragma unroll
            for (int t = 0; t < 8; t++) {
                int k2 = (tid + t * 256) & 15;
                ra[t] = *(const float2*)(aRow[t] + kt + 32 + 2 * k2);
            }
            #pragma unroll
            for (int t = 0; t < 4; t++) {
                int idx = tid + t * 256;
                int kr = idx >> 5, n2 = idx & 31;
                rw[t] = *(const float2*)&W[(size_t)(kt + 32 + kr) * INNER + col0 + 2 * n2];
            }
        }
        __syncthreads();

        #pragma unroll
        for (int kk = 0; kk < 2; kk++) {
            uint32_t a[2][4];
            #pragma unroll
            for (int mt = 0; mt < 2; mt++)
                ldsm_x4(a[mt][0], a[mt][1], a[mt][2], a[mt][3],
                        uA + (wy * 32 + mt * 16) * 80 + kk * 32 + offA);
            #pragma unroll
            for (int p = 0; p < 2; p++) {
                uint32_t b0, b1, b2, b3;
                ldsm_x4_t(b0, b1, b2, b3,
                          uW + kk * 16 * 144 + (wx * 32 + p * 16) * 2 + offW);
                mma_f16(acc[0][2 * p],     a[0][0], a[0][1], a[0][2], a[0][3], b0, b1);
                mma_f16(acc[0][2 * p + 1], a[0][0], a[0][1], a[0][2], a[0][3], b2, b3);
                mma_f16(acc[1][2 * p],     a[1][0], a[1][1], a[1][2], a[1][3], b0, b1);
                mma_f16(acc[1][2 * p + 1], a[1][0], a[1][1], a[1][2], a[1][3], b2, b3);
            }
        }
    }

    #pragma unroll
    for (int mt = 0; mt < 2; mt++) {
        #pragma unroll
        for (int hh = 0; hh < 2; hh++) {
            int slot = slot0 + wy * 32 + mt * 16 + g + 8 * hh;
            bool ok = slot < segEnd;
            #pragma unroll
            for (int n = 0; n < 4; n++) {
                int c = col0 + wx * 32 + n * 8 + 2 * qd;
                float v0 = (acc[mt][n][hh * 2 + 0] + bias[c]) * scl;
                float v1 = (acc[mt][n][hh * 2 + 1] + bias[c + 1]) * scl;
                if (ok) {
                    int hidx = c >> 6, d = c & 63;
                    *(__half2*)&dst[((size_t)(bhBase + hidx) * LTOT + slot) * DHEAD + d] =
                        __floats2half2_rn(v0, v1);
                }
            }
        }
    }
}

// ---------------------------------------------------------------------------
// Fused QKV projections: Q/K compacted, V dense (+fused vpart reduction).
// ---------------------------------------------------------------------------
__global__ __launch_bounds__(256) void qkv_kernel(
        const float* __restrict__ nodes, const float* __restrict__ edges,
        const float* Wq, const float* Wk, const float* Wv,
        const float* bq, const float* bk, const float* bv,
        const float* Weq, const float* Wek, const float* Wev,
        const float* beq, const float* bek, const float* bev,
        __half* qp, __half* kp, __half* vp, float qscale) {
    const int t = blockIdx.x;
    if (t < 256) {
        const int pr = t >> 7;
        const int rem = t & 127;
        const int b = rem >> 6;
        const int rt = (rem >> 3) & 7;
        const int ct = rem & 7;
        const int nn = g_nn[b];
        const int slot0 = rt * 128;
        if (slot0 >= nn) return;
        gemm_qk_compact(nodes + (size_t)b * NN * DIMN,
                        pr ? Wk : Wq, pr ? bk : bq, pr ? kp : qp,
                        pr ? 1.f : qscale, DIMN, 0,
                        g_kidx + b * LTOT, slot0, nn, b * HEADS, ct * 64);
    } else if (t < 768) {
        const int u = t - 256;
        const int pr = u >> 8;
        const int rem = u & 255;
        const int b = rem >> 7;
        const int rt = (rem >> 3) & 15;
        const int ct = rem & 7;
        const int nn = g_nn[b];
        const int nk = g_nk[b];
        const int slot0 = nn + rt * 128;
        if (slot0 >= nk) return;
        gemm_qk_compact(edges + (size_t)b * EE * EDIM,
                        pr ? Wek : Weq, pr ? bek : beq, pr ? kp : qp,
                        pr ? 1.f : qscale, EDIM, NN,
                        g_kidx + b * LTOT, slot0, nk, b * HEADS, ct * 64);
    } else {
        const int u = t - 768;
        if (u < 128) {
            const int row0 = (u >> 3) * 128, col0 = (u & 7) * 64;
            gemm_body<false, 0, true>(nodes, Wv, bv, vp, 1.f,
                                      128, 512, 1024, 1024, 0, 0, row0, col0, 0);
        } else {
            const int v = u - 128;
            const int row0 = (v >> 3) * 128, col0 = (v & 7) * 64;
            gemm_body<false, 0, true>(edges, Wev, bev, vp, 1.f,
                                      256, 512, 2048, 2048, 0, 1024, row0, col0, 8);
        }
    }
}

// ---------------------------------------------------------------------------
// Fused output projections (node + edge) in one launch. 160 CTAs.
// ---------------------------------------------------------------------------
__global__ __launch_bounds__(256) void outproj_kernel(
        const float* __restrict__ Wo, const float* __restrict__ bo,
        const float* __restrict__ Weo, const float* __restrict__ beo,
        float* __restrict__ out) {
    const int t = blockIdx.x;
    if (t < 32) {
        const int col0 = (t & 1) * 64, row0 = (t >> 1) * 128;
        gemm_body<true, 1, false>(g_oh, Wo, bo, out, 1.f,
                                  512, 128, 1024, 3072, 0, 0, row0, col0, 0);
    } else {
        const int u = t - 32;
        const int col0 = (u & 3) * 64, row0 = (u >> 2) * 128;
        gemm_body<true, 1, false>(g_oh, Weo, beo, out + 2 * 1024 * 128, 1.f,
                                  512, 256, 2048, 3072, 1024, 0, row0, col0, 0);
    }
}

// ---------------------------------------------------------------------------
// Flash attention over compacted rows (R13/R14 form). Idle CTAs patch masked
// rows of g_oh from g_vpart (uniform softmax = Vmean).
// ---------------------------------------------------------------------------
#define KVSTR 72
#define KVBUF_H (64 * KVSTR)
#define KVBUF_B (KVBUF_H * 2)
#define ATTN_SMEM_BYTES (4 * KVBUF_B)

__device__ __forceinline__ void patch_tiles(int b, int h, int bh, int pstart, int pstep) {
    __shared__ float vms[64];
    const int tid = threadIdx.x;
    if (tid < 64) {
        float s = 0.f;
        #pragma unroll
        for (int c = 0; c < VCH; c++)
            s += g_vpart[((size_t)bh * VCH + c) * DHEAD + tid];
        vms[tid] = s * (1.0f / LTOT);
    }
    __syncthreads();
    const int dg = tid & 7;
    uint4 hv;
    hv.x = packh2(vms[dg * 8 + 0], vms[dg * 8 + 1]);
    hv.y = packh2(vms[dg * 8 + 2], vms[dg * 8 + 3]);
    hv.z = packh2(vms[dg * 8 + 4], vms[dg * 8 + 5]);
    hv.w = packh2(vms[dg * 8 + 6], vms[dg * 8 + 7]);
    for (int p = pstart; p < 24; p += pstep) {
        #pragma unroll
        for (int pass = 0; pass < 4; pass++) {
            int r = p * 128 + pass * 32 + (tid >> 3);
            if (!g_mask[b * LTOT + r])
                *(uint4*)&g_oh[(size_t)(b * LTOT + r) * INNER + h * DHEAD + dg * 8] = hv;
        }
    }
}

__global__ __launch_bounds__(256, 2) void attn_f16_kernel() {
    const int bh = blockIdx.y;
    const int b = bh >> 3, h = bh & 7;
    const int nk = g_nk[b];
    const int q0 = blockIdx.x * 128;
    const int qtiles = (nk + 127) >> 7;
    const int nidle = 24 - qtiles;

    if (q0 >= nk) {
        patch_tiles(b, h, bh, blockIdx.x - qtiles, nidle);
        return;
    }

    extern __shared__ __align__(16) char smraw[];
    __half* Kh = (__half*)smraw;                 // [2][64][72]
    __half* Vh = (__half*)(smraw + 2 * KVBUF_B); // [2][64][72]

    const int tid = threadIdx.x;
    const int warp = tid >> 5, lane = tid & 31;
    const int g = lane >> 2, qd = lane & 3;

    const __half* Qg = g_qh + (size_t)bh * LTOT * DHEAD;   // compacted
    const __half* Kg = g_kh + (size_t)bh * LTOT * DHEAD;   // compacted
    const __half* Vg = g_vh + (size_t)bh * LTOT * DHEAD;   // full
    const int* kidx = g_kidx + b * LTOT;
    const int NIT = (nk + 63) >> 6;

    const uint32_t uK = sptr(Kh), uV = sptr(Vh);
    const int offA = ((lane & 7) + ((lane >> 3) & 1) * 8) * 144 + (lane >> 4) * 16;
    const int offK = ((lane & 7) + ((lane >> 4) & 1) * 8) * 144 + ((lane >> 3) & 1) * 16;

    const int prow = tid >> 3;                   // 0..31
    const int pch = (tid & 7) * 16;              // byte offset 0..112

    // Prologue: load tile 0 (K dense, V gathered)
    {
        #pragma unroll
        for (int rr = 0; rr < 2; rr++) {
            int r = prow + rr * 32;
            int kdrow = (r < nk) ? r : 0;
            int vrow = (r < nk) ? kidx[r] : 0;
            cp16(uK + r * 144 + pch, Kg + (size_t)kdrow * 64 + (pch >> 1));
            cp16(uV + r * 144 + pch, Vg + (size_t)vrow * 64 + (pch >> 1));
        }
        cp_commit();
    }

    // Query rows: dense compacted slots
    const int qr_a = q0 + warp * 16 + g;
    const int qr_b = qr_a + 8;
    const int valid0 = qr_a < nk;
    const int valid1 = qr_b < nk;

    uint32_t qa[4][4];
    {
        const __half* qr0p = Qg + (size_t)(valid0 ? qr_a : 0) * DHEAD;
        const __half* qr1p = Qg + (size_t)(valid1 ? qr_b : 0) * DHEAD;
        #pragma unroll
        for (int kk = 0; kk < 4; kk++) {
            int c = kk * 16 + 2 * qd;
            qa[kk][0] = *(const uint32_t*)(qr0p + c);
            qa[kk][1] = *(const uint32_t*)(qr1p + c);
            qa[kk][2] = *(const uint32_t*)(qr0p + c + 8);
            qa[kk][3] = *(const uint32_t*)(qr1p + c + 8);
        }
    }

    float m_i[2] = {-FLT_MAX, -FLT_MAX};
    float l_i[2] = {0.f, 0.f};
    float o[8][4] = {};

    for (int it = 0; it < NIT; it++) {
        const int bf = it & 1;
        const int k0 = it * 64;
        cp_wait0();
        __syncthreads();

        if (it + 1 < NIT) {
            uint32_t uKn = uK + (bf ^ 1) * KVBUF_B;
            uint32_t uVn = uV + (bf ^ 1) * KVBUF_B;
            #pragma unroll
            for (int rr = 0; rr < 2; rr++) {
                int r = prow + rr * 32;
                int gi = k0 + 64 + r;
                int kdrow = (gi < nk) ? gi : 0;
                int vrow = (gi < nk) ? kidx[gi] : 0;
                cp16(uKn + r * 144 + pch, Kg + (size_t)kdrow * 64 + (pch >> 1));
                cp16(uVn + r * 144 + pch, Vg + (size_t)vrow * 64 + (pch >> 1));
            }
            cp_commit();
        }

        const uint32_t uKb = uK + bf * KVBUF_B;
        const uint32_t uVb = uV + bf * KVBUF_B;

        // ---- S = Q @ K^T ----
        float s[8][4] = {};
        #pragma unroll
        for (int kk = 0; kk < 4; kk++) {
            #pragma unroll
            for (int p = 0; p < 4; p++) {
                uint32_t b0, b1, b2, b3;
                ldsm_x4(b0, b1, b2, b3, uKb + p * 16 * 144 + kk * 32 + offK);
                mma_f16(s[2 * p],     qa[kk][0], qa[kk][1], qa[kk][2], qa[kk][3], b0, b1);
                mma_f16(s[2 * p + 1], qa[kk][0], qa[kk][1], qa[kk][2], qa[kk][3], b2, b3);
            }
        }

        // ---- tail masking (key side) ----
        if (k0 + 64 > nk) {
            #pragma unroll
            for (int nt = 0; nt < 8; nt++) {
                int j0 = k0 + nt * 8 + 2 * qd;
                if (j0 >= nk)     { s[nt][0] = -FLT_MAX; s[nt][2] = -FLT_MAX; }
                if (j0 + 1 >= nk) { s[nt][1] = -FLT_MAX; s[nt][3] = -FLT_MAX; }
            }
        }

        // ---- online softmax (base-2) ----
        #pragma unroll
        for (int hh = 0; hh < 2; hh++) {
            float mx = -FLT_MAX;
            #pragma unroll
            for (int nt = 0; nt < 8; nt++)
                mx = fmaxf(mx, fmaxf(s[nt][hh * 2], s[nt][hh * 2 + 1]));
            mx = fmaxf(mx, __shfl_xor_sync(0xffffffffu, mx, 1));
            mx = fmaxf(mx, __shfl_xor_sync(0xffffffffu, mx, 2));
            float mnew = fmaxf(m_i[hh], mx);
            float corr = fexp2(m_i[hh] - mnew);
            m_i[hh] = mnew;
            float rs = 0.f;
            #pragma unroll
            for (int nt = 0; nt < 8; nt++) {
                float p0 = fexp2(s[nt][hh * 2]     - mnew);
                float p1 = fexp2(s[nt][hh * 2 + 1] - mnew);
                rs += p0 + p1;
                s[nt][hh * 2]     = p0;
                s[nt][hh * 2 + 1] = p1;
            }
            rs += __shfl_xor_sync(0xffffffffu, rs, 1);
            rs += __shfl_xor_sync(0xffffffffu, rs, 2);
            l_i[hh] = l_i[hh] * corr + rs;
            #pragma unroll
            for (int nt = 0; nt < 8; nt++) {
                o[nt][hh * 2]     *= corr;
                o[nt][hh * 2 + 1] *= corr;
            }
        }

        // ---- O += P @ V ----
        #pragma unroll
        for (int jj = 0; jj < 4; jj++) {
            uint32_t pa0 = packh2(s[2 * jj][0],     s[2 * jj][1]);
            uint32_t pa1 = packh2(s[2 * jj][2],     s[2 * jj][3]);
            uint32_t pa2 = packh2(s[2 * jj + 1][0], s[2 * jj + 1][1]);
            uint32_t pa3 = packh2(s[2 * jj + 1][2], s[2 * jj + 1][3]);
            #pragma unroll
            for (int p = 0; p < 4; p++) {
                uint32_t b0, b1, b2, b3;
                ldsm_x4_t(b0, b1, b2, b3, uVb + jj * 16 * 144 + p * 32 + offA);
                mma_f16(o[2 * p],     pa0, pa1, pa2, pa3, b0, b1);
                mma_f16(o[2 * p + 1], pa0, pa1, pa2, pa3, b2, b3);
            }
        }
    }

    // ---- epilogue: normalize + scatter to original row indices ----
    #pragma unroll
    for (int hh = 0; hh < 2; hh++) {
        if (!(hh ? valid1 : valid0)) continue;
        const int qrow = kidx[hh ? qr_b : qr_a];
        float inv = 1.f / l_i[hh];
        __half* dstp = &g_oh[(size_t)(b * LTOT + qrow) * INNER + h * DHEAD];
        #pragma unroll
        for (int nt = 0; nt < 8; nt++) {
            int d0 = nt * 8 + 2 * qd;
            *(__half2*)&dstp[d0] =
                __floats2half2_rn(o[nt][hh * 2] * inv, o[nt][hh * 2 + 1] * inv);
        }
    }

    // Fallback: if no idle CTAs exist (nk > 2944), last CTA patches everything.
    if (nidle == 0 && blockIdx.x == 23) {
        __syncthreads();
        patch_tiles(b, h, bh, 0, 1);
    }
}

// ---------------------------------------------------------------------------
// kernel_launch
// ---------------------------------------------------------------------------
extern "C" void kernel_launch(void* const* d_in, const int* in_sizes, int n_in,
                              void* d_out, int out_size) {
    const float* nodes = (const float*)d_in[0];
    const float* edges = (const float*)d_in[1];
    const unsigned char* mask_raw = (const unsigned char*)d_in[2];
    const float* Wq  = (const float*)d_in[3];
    const float* bq  = (const float*)d_in[4];
    const float* Wk  = (const float*)d_in[5];
    const float* bk  = (const float*)d_in[6];
    const float* Wv  = (const float*)d_in[7];
    const float* bv  = (const float*)d_in[8];
    const float* Weq = (const float*)d_in[9];
    const float* beq = (const float*)d_in[10];
    const float* Wek = (const float*)d_in[11];
    const float* bek = (const float*)d_in[12];
    const float* Wev = (const float*)d_in[13];
    const float* bev = (const float*)d_in[14];
    const float* Wo  = (const float*)d_in[15];
    const float* bo  = (const float*)d_in[16];
    const float* Weo = (const float*)d_in[17];
    const float* beo = (const float*)d_in[18];
    float* out = (float*)d_out;

    void *qp, *kp, *vp;
    cudaGetSymbolAddress(&qp, g_qh);
    cudaGetSymbolAddress(&kp, g_kh);
    cudaGetSymbolAddress(&vp, g_vh);

    mask_kernel<<<BSZ, 256>>>(mask_raw);

    // QKV: Q/K compacted, V full with fused vpart reduction — one launch
    qkv_kernel<<<1152, 256>>>(
        nodes, edges, Wq, Wk, Wv, bq, bk, bv,
        Weq, Wek, Wev, beq, bek, bev,
        (__half*)qp, (__half*)kp, (__half*)vp, SCALE * LOG2E);

    // Flash attention + patch in idle CTAs
    cudaFuncSetAttribute(attn_f16_kernel,
                         cudaFuncAttributeMaxDynamicSharedMemorySize, ATTN_SMEM_BYTES);
    attn_f16_kernel<<<dim3(24, BSZ * HEADS), 256, ATTN_SMEM_BYTES>>>();

    // Both output projections in one launch
    outproj_kernel<<<160, 256>>>(Wo, bo, Weo, beo, out);
}

// round 16
// speedup vs baseline: 1.4982x; 1.1484x over previous
#include <cuda_runtime.h>
#include <cuda_fp16.h>
#include <float.h>
#include <math.h>
#include <stdint.h>

// Problem constants
#define BSZ   2
#define NN    1024
#define EE    2048
#define LTOT  3072
#define DIMN  128
#define EDIM  256
#define HEADS 8
#define DHEAD 64
#define INNER 512
#define SCALE 0.125f
#define LOG2E 1.4426950408889634f
#define VCH   24                                // vmean chunks per (b,h)

// fp16 conversion buffer regions (element offsets)
#define OFF_NODES 0
#define OFF_EDGES 262144
#define OFF_WQ    1310720
#define OFF_WK    1376256
#define OFF_WV    1441792
#define OFF_WEQ   1507328
#define OFF_WEK   1638400
#define OFF_WEV   1769472
#define OFF_WO    1900544
#define OFF_WEO   1966080
#define H16_TOTAL 2097152

// Scratch
__device__ __half g_h16[H16_TOTAL];                   // fp16 inputs + weights
__device__ __half g_qh[BSZ * HEADS * LTOT * DHEAD];   // COMPACTED rows, pre-scaled
__device__ __half g_kh[BSZ * HEADS * LTOT * DHEAD];   // COMPACTED rows
__device__ __half g_vh[BSZ * HEADS * LTOT * DHEAD];   // full
__device__ __half g_oh[BSZ * LTOT * INNER];
__device__ int    g_mask[BSZ * LTOT];
__device__ int    g_kidx[BSZ * LTOT];
__device__ int    g_nk[BSZ];
__device__ int    g_nn[BSZ];
__device__ float  g_vpart[BSZ * HEADS * VCH * DHEAD];

// ---------------------------------------------------------------------------
// PTX helpers
// ---------------------------------------------------------------------------
__device__ __forceinline__ uint32_t sptr(const void* p) {
    return (uint32_t)__cvta_generic_to_shared(p);
}
__device__ __forceinline__ void ldsm_x4(uint32_t& r0, uint32_t& r1,
                                        uint32_t& r2, uint32_t& r3, uint32_t addr) {
    asm volatile("ldmatrix.sync.aligned.m8n8.x4.shared.b16 {%0,%1,%2,%3}, [%4];"
                 : "=r"(r0), "=r"(r1), "=r"(r2), "=r"(r3) : "r"(addr));
}
__device__ __forceinline__ void ldsm_x4_t(uint32_t& r0, uint32_t& r1,
                                          uint32_t& r2, uint32_t& r3, uint32_t addr) {
    asm volatile("ldmatrix.sync.aligned.m8n8.x4.trans.shared.b16 {%0,%1,%2,%3}, [%4];"
                 : "=r"(r0), "=r"(r1), "=r"(r2), "=r"(r3) : "r"(addr));
}
__device__ __forceinline__ void mma_f16(float c[4],
                                        uint32_t a0, uint32_t a1, uint32_t a2, uint32_t a3,
                                        uint32_t b0, uint32_t b1) {
    asm volatile(
        "mma.sync.aligned.m16n8k16.row.col.f32.f16.f16.f32 "
        "{%0,%1,%2,%3}, {%4,%5,%6,%7}, {%8,%9}, {%0,%1,%2,%3};"
        : "+f"(c[0]), "+f"(c[1]), "+f"(c[2]), "+f"(c[3])
        : "r"(a0), "r"(a1), "r"(a2), "r"(a3), "r"(b0), "r"(b1));
}
__device__ __forceinline__ void cp16(uint32_t dst, const void* src) {
    asm volatile("cp.async.cg.shared.global [%0], [%1], 16;" :: "r"(dst), "l"(src));
}
__device__ __forceinline__ void cp_commit() {
    asm volatile("cp.async.commit_group;");
}
__device__ __forceinline__ void cp_wait0() {
    asm volatile("cp.async.wait_group 0;");
}
__device__ __forceinline__ uint32_t packh2(float x, float y) {
    __half2 h = __floats2half2_rn(x, y);
    return *reinterpret_cast<uint32_t*>(&h);
}
__device__ __forceinline__ float fexp2(float x) {
    float y;
    asm("ex2.approx.ftz.f32 %0, %1;" : "=f"(y) : "f"(x));
    return y;
}

// ---------------------------------------------------------------------------
// Mask decode + compaction (2 CTAs) fused with fp32->fp16 conversion of all
// GEMM operands (128 CTAs, 16384 elements each, deterministic).
// ---------------------------------------------------------------------------
__global__ __launch_bounds__(256) void mask_convert_kernel(
        const unsigned char* __restrict__ raw,
        const float* nodes, const float* edges,
        const float* Wq, const float* Wk, const float* Wv,
        const float* Weq, const float* Wek, const float* Wev,
        const float* Wo, const float* Weo) {
    const int tid = threadIdx.x;
    if (blockIdx.x < 2) {
        __shared__ int partial[256];
        __shared__ int pfx[256];
        __shared__ int pnode[256];
        const int n = BSZ * LTOT;
        const int b = blockIdx.x;

        int cnt = 0;
        for (int i = tid; i < n; i += 256) cnt += (raw[i] != 0);
        partial[tid] = cnt;
        __syncthreads();
        for (int s = 128; s > 0; s >>= 1) {
            if (tid < s) partial[tid] += partial[tid + s];
            __syncthreads();
        }
        const int width1 = partial[0] > (n * 3 / 8);
        const int* raw32 = (const int*)raw;

        int bits[12];
        int myc = 0, mync = 0;
        #pragma unroll
        for (int i = 0; i < 12; i++) {
            int li = tid * 12 + i;
            int gi = b * LTOT + li;
            int v = width1 ? (raw[gi] != 0) : (raw32[gi] != 0);
            g_mask[gi] = v;
            bits[i] = v;
            myc += v;
            if (li < NN) mync += v;
        }
        pfx[tid] = myc;
        pnode[tid] = mync;
        __syncthreads();
        for (int s = 128; s > 0; s >>= 1) {
            if (tid < s) pnode[tid] += pnode[tid + s];
            __syncthreads();
        }
        if (tid == 0) {
            g_nn[b] = pnode[0];
            int acc = 0;
            for (int t = 0; t < 256; t++) { int c = pfx[t]; pfx[t] = acc; acc += c; }
            g_nk[b] = acc;
        }
        __syncthreads();
        int off = b * LTOT + pfx[tid];
        #pragma unroll
        for (int i = 0; i < 12; i++)
            if (bits[i]) g_kidx[off++] = tid * 12 + i;
    } else {
        const int u = blockIdx.x - 2;
        const float* src; int doff, chunk;
        if      (u < 16)  { src = nodes; doff = OFF_NODES; chunk = u; }
        else if (u < 80)  { src = edges; doff = OFF_EDGES; chunk = u - 16; }
        else if (u < 84)  { src = Wq;    doff = OFF_WQ;    chunk = u - 80; }
        else if (u < 88)  { src = Wk;    doff = OFF_WK;    chunk = u - 84; }
        else if (u < 92)  { src = Wv;    doff = OFF_WV;    chunk = u - 88; }
        else if (u < 100) { src = Weq;   doff = OFF_WEQ;   chunk = u - 92; }
        else if (u < 108) { src = Wek;   doff = OFF_WEK;   chunk = u - 100; }
        else if (u < 116) { src = Wev;   doff = OFF_WEV;   chunk = u - 108; }
        else if (u < 120) { src = Wo;    doff = OFF_WO;    chunk = u - 116; }
        else              { src = Weo;   doff = OFF_WEO;   chunk = u - 120; }
        const int base = chunk * 16384;
        #pragma unroll
        for (int j = 0; j < 16; j++) {
            int e = (j * 256 + tid) * 4;
            float4 v = *(const float4*)(src + base + e);
            uint2 o;
            o.x = packh2(v.x, v.y);
            o.y = packh2(v.z, v.w);
            *(uint2*)(g_h16 + doff + base + e) = o;
        }
    }
}

// ---------------------------------------------------------------------------
// All-fp16 GEMM body: 128x64 tile, BK=64, cp.async double-buffered smem.
// Stages: [sA0][sA1][sW0][sW1]; rows 144B (72 halves) -> ldsm conflict-free.
// VSUM: fused per-CTA row reduction to g_vpart (V projection).
// DSTMODE 0: scatter fp16 [B,H,L,D]; 1: fp32 [m, Ncols].
// ---------------------------------------------------------------------------
#define ASTG 18432                               // 128*144 bytes
#define WSTG 9216                                // 64*144 bytes
#define GEMM_SMEM (2 * ASTG + 2 * WSTG)          // 55296

template <int DSTMODE, bool VSUM>
__device__ __forceinline__ void gemm16_body(
        const __half* __restrict__ Ah, const __half* __restrict__ Wh,
        const float* __restrict__ bias, void* __restrict__ dst, float scl,
        int K, int Ncols, int rowsPerBatch, int aBatchStride, int aSeqOff,
        int dstSeqOff, int row0, int col0, int chunkOff, char* smem) {
    const int tid = threadIdx.x;
    const int warp = tid >> 5, lane = tid & 31;
    const int g = lane >> 2, qd = lane & 3;
    const int wy = warp >> 1, wx = warp & 1;

    const uint32_t uA = sptr(smem);
    const uint32_t uW = uA + 2 * ASTG;
    const int offA = ((lane & 7) + ((lane >> 3) & 1) * 8) * 144 + (lane >> 4) * 16;
    const int offW = offA;

    // Per-thread cp.async descriptors: A 4 chunks, W 2 chunks
    size_t aoff[4];
    int dA[4];
    #pragma unroll
    for (int t = 0; t < 4; t++) {
        int idx = tid + t * 256;
        int i = idx >> 3, c = idx & 7;
        int m = row0 + i;
        int bb = m / rowsPerBatch;
        int r = m - bb * rowsPerBatch;
        aoff[t] = (size_t)(bb * aBatchStride + aSeqOff + r) * K + c * 8;
        dA[t] = i * 144 + c * 16;
    }
    size_t woff[2];
    int dW[2];
    #pragma unroll
    for (int t = 0; t < 2; t++) {
        int idx = tid + t * 256;
        int kr = idx >> 3, c = idx & 7;
        woff[t] = (size_t)kr * Ncols + col0 + c * 8;
        dW[t] = kr * 144 + c * 16;
    }

    const int NIT = K >> 6;
    // Prologue
    #pragma unroll
    for (int t = 0; t < 4; t++) cp16(uA + dA[t], Ah + aoff[t]);
    #pragma unroll
    for (int t = 0; t < 2; t++) cp16(uW + dW[t], Wh + woff[t]);
    cp_commit();

    float acc[2][4][4] = {};

    for (int it = 0; it < NIT; it++) {
        const int bf = it & 1;
        cp_wait0();
        __syncthreads();

        if (it + 1 < NIT) {
            const int kt = (it + 1) * 64;
            const uint32_t uAn = uA + (bf ^ 1) * ASTG;
            const uint32_t uWn = uW + (bf ^ 1) * WSTG;
            #pragma unroll
            for (int t = 0; t < 4; t++) cp16(uAn + dA[t], Ah + aoff[t] + kt);
            #pragma unroll
            for (int t = 0; t < 2; t++) cp16(uWn + dW[t], Wh + woff[t] + (size_t)kt * Ncols);
            cp_commit();
        }

        const uint32_t uAb = uA + bf * ASTG;
        const uint32_t uWb = uW + bf * WSTG;
        #pragma unroll
        for (int kk = 0; kk < 4; kk++) {
            uint32_t a[2][4];
            #pragma unroll
            for (int mt = 0; mt < 2; mt++)
                ldsm_x4(a[mt][0], a[mt][1], a[mt][2], a[mt][3],
                        uAb + (wy * 32 + mt * 16) * 144 + kk * 32 + offA);
            #pragma unroll
            for (int p = 0; p < 2; p++) {
                uint32_t b0, b1, b2, b3;
                ldsm_x4_t(b0, b1, b2, b3,
                          uWb + kk * 16 * 144 + (wx * 32 + p * 16) * 2 + offW);
                mma_f16(acc[0][2 * p],     a[0][0], a[0][1], a[0][2], a[0][3], b0, b1);
                mma_f16(acc[0][2 * p + 1], a[0][0], a[0][1], a[0][2], a[0][3], b2, b3);
                mma_f16(acc[1][2 * p],     a[1][0], a[1][1], a[1][2], a[1][3], b0, b1);
                mma_f16(acc[1][2 * p + 1], a[1][0], a[1][1], a[1][2], a[1][3], b2, b3);
            }
        }
    }
    __syncthreads();   // smem dead; VSUM reuses it

    float vsum[4][2];
    if (VSUM) {
        #pragma unroll
        for (int n = 0; n < 4; n++) { vsum[n][0] = 0.f; vsum[n][1] = 0.f; }
    }

    #pragma unroll
    for (int mt = 0; mt < 2; mt++) {
        #pragma unroll
        for (int hh = 0; hh < 2; hh++) {
            int m = row0 + wy * 32 + mt * 16 + g + 8 * hh;
            int bb = m / rowsPerBatch;
            int r = m - bb * rowsPerBatch;
            #pragma unroll
            for (int n = 0; n < 4; n++) {
                int c = col0 + wx * 32 + n * 8 + 2 * qd;
                float v0 = (acc[mt][n][hh * 2 + 0] + bias[c]) * scl;
                float v1 = (acc[mt][n][hh * 2 + 1] + bias[c + 1]) * scl;
                if (VSUM) { vsum[n][0] += v0; vsum[n][1] += v1; }
                if (DSTMODE == 0) {
                    int hidx = c >> 6, d = c & 63;
                    __half* dh = (__half*)dst;
                    *(__half2*)&dh[((size_t)(bb * HEADS + hidx) * LTOT +
                                    dstSeqOff + r) * DHEAD + d] = __floats2half2_rn(v0, v1);
                } else {
                    float* df = (float*)dst;
                    *(float2*)&df[(size_t)m * Ncols + c] = make_float2(v0, v1);
                }
            }
        }
    }

    if (VSUM) {
        #pragma unroll
        for (int n = 0; n < 4; n++)
            #pragma unroll
            for (int e = 0; e < 2; e++) {
                float x = vsum[n][e];
                x += __shfl_xor_sync(0xffffffffu, x, 4);
                x += __shfl_xor_sync(0xffffffffu, x, 8);
                x += __shfl_xor_sync(0xffffffffu, x, 16);
                vsum[n][e] = x;
            }
        float* vs = (float*)smem;
        if (g == 0) {
            #pragma unroll
            for (int n = 0; n < 4; n++) {
                vs[wy * 64 + wx * 32 + n * 8 + 2 * qd + 0] = vsum[n][0];
                vs[wy * 64 + wx * 32 + n * 8 + 2 * qd + 1] = vsum[n][1];
            }
        }
        __syncthreads();
        if (tid < DHEAD) {
            float s = vs[tid] + vs[64 + tid] + vs[128 + tid] + vs[192 + tid];
            int bb = row0 / rowsPerBatch;
            int h = col0 >> 6;
            int chunk = (row0 - bb * rowsPerBatch) / 128 + chunkOff;
            g_vpart[((size_t)(bb * HEADS + h) * VCH + chunk) * DHEAD + tid] = s;
        }
    }
}

// ---------------------------------------------------------------------------
// Compacted-row fp16 GEMM for Q/K projections (gather via kidx).
// ---------------------------------------------------------------------------
__device__ __forceinline__ void gemm16_compact(
        const __half* __restrict__ Ah, const __half* __restrict__ Wh,
        const float* __restrict__ bias, __half* __restrict__ dst, float scl,
        int K, int srcOff, const int* __restrict__ kidx,
        int slot0, int segEnd, int bhBase, int col0, char* smem) {
    const int tid = threadIdx.x;
    const int warp = tid >> 5, lane = tid & 31;
    const int g = lane >> 2, qd = lane & 3;
    const int wy = warp >> 1, wx = warp & 1;

    const uint32_t uA = sptr(smem);
    const uint32_t uW = uA + 2 * ASTG;
    const int offA = ((lane & 7) + ((lane >> 3) & 1) * 8) * 144 + (lane >> 4) * 16;
    const int offW = offA;

    size_t aoff[4];
    int dA[4];
    #pragma unroll
    for (int t = 0; t < 4; t++) {
        int idx = tid + t * 256;
        int i = idx >> 3, c = idx & 7;
        int slot = slot0 + i;
        int src = (slot < segEnd) ? (kidx[slot] - srcOff) : 0;
        aoff[t] = (size_t)src * K + c * 8;
        dA[t] = i * 144 + c * 16;
    }
    size_t woff[2];
    int dW[2];
    #pragma unroll
    for (int t = 0; t < 2; t++) {
        int idx = tid + t * 256;
        int kr = idx >> 3, c = idx & 7;
        woff[t] = (size_t)kr * INNER + col0 + c * 8;
        dW[t] = kr * 144 + c * 16;
    }

    const int NIT = K >> 6;
    #pragma unroll
    for (int t = 0; t < 4; t++) cp16(uA + dA[t], Ah + aoff[t]);
    #pragma unroll
    for (int t = 0; t < 2; t++) cp16(uW + dW[t], Wh + woff[t]);
    cp_commit();

    float acc[2][4][4] = {};

    for (int it = 0; it < NIT; it++) {
        const int bf = it & 1;
        cp_wait0();
        __syncthreads();

        if (it + 1 < NIT) {
            const int kt = (it + 1) * 64;
            const uint32_t uAn = uA + (bf ^ 1) * ASTG;
            const uint32_t uWn = uW + (bf ^ 1) * WSTG;
            #pragma unroll
            for (int t = 0; t < 4; t++) cp16(uAn + dA[t], Ah + aoff[t] + kt);
            #pragma unroll
            for (int t = 0; t < 2; t++) cp16(uWn + dW[t], Wh + woff[t] + (size_t)kt * INNER);
            cp_commit();
        }

        const uint32_t uAb = uA + bf * ASTG;
        const uint32_t uWb = uW + bf * WSTG;
        #pragma unroll
        for (int kk = 0; kk < 4; kk++) {
            uint32_t a[2][4];
            #pragma unroll
            for (int mt = 0; mt < 2; mt++)
                ldsm_x4(a[mt][0], a[mt][1], a[mt][2], a[mt][3],
                        uAb + (wy * 32 + mt * 16) * 144 + kk * 32 + offA);
            #pragma unroll
            for (int p = 0; p < 2; p++) {
                uint32_t b0, b1, b2, b3;
                ldsm_x4_t(b0, b1, b2, b3,
                          uWb + kk * 16 * 144 + (wx * 32 + p * 16) * 2 + offW);
                mma_f16(acc[0][2 * p],     a[0][0], a[0][1], a[0][2], a[0][3], b0, b1);
                mma_f16(acc[0][2 * p + 1], a[0][0], a[0][1], a[0][2], a[0][3], b2, b3);
                mma_f16(acc[1][2 * p],     a[1][0], a[1][1], a[1][2], a[1][3], b0, b1);
                mma_f16(acc[1][2 * p + 1], a[1][0], a[1][1], a[1][2], a[1][3], b2, b3);
            }
        }
    }

    #pragma unroll
    for (int mt = 0; mt < 2; mt++) {
        #pragma unroll
        for (int hh = 0; hh < 2; hh++) {
            int slot = slot0 + wy * 32 + mt * 16 + g + 8 * hh;
            bool ok = slot < segEnd;
            #pragma unroll
            for (int n = 0; n < 4; n++) {
                int c = col0 + wx * 32 + n * 8 + 2 * qd;
                float v0 = (acc[mt][n][hh * 2 + 0] + bias[c]) * scl;
                float v1 = (acc[mt][n][hh * 2 + 1] + bias[c + 1]) * scl;
                if (ok) {
                    int hidx = c >> 6, d = c & 63;
                    *(__half2*)&dst[((size_t)(bhBase + hidx) * LTOT + slot) * DHEAD + d] =
                        __floats2half2_rn(v0, v1);
                }
            }
        }
    }
}

// ---------------------------------------------------------------------------
// Fused QKV projections: Q/K compacted, V dense (+fused vpart reduction).
// 1152 CTAs: [0,256) node Q/K, [256,768) edge Q/K, [768,1152) V dense.
// ---------------------------------------------------------------------------
__global__ __launch_bounds__(256) void qkv_kernel(
        const float* bq, const float* bk, const float* bv,
        const float* beq, const float* bek, const float* bev,
        __half* qp, __half* kp, __half* vp, float qscale) {
    extern __shared__ char gsm[];
    const int t = blockIdx.x;
    if (t < 256) {
        const int pr = t >> 7;
        const int rem = t & 127;
        const int b = rem >> 6;
        const int rt = (rem >> 3) & 7;
        const int ct = rem & 7;
        const int nn = g_nn[b];
        const int slot0 = rt * 128;
        if (slot0 >= nn) return;
        gemm16_compact(g_h16 + OFF_NODES + (size_t)b * NN * DIMN,
                       g_h16 + (pr ? OFF_WK : OFF_WQ),
                       pr ? bk : bq, pr ? kp : qp,
                       pr ? 1.f : qscale, DIMN, 0,
                       g_kidx + b * LTOT, slot0, nn, b * HEADS, ct * 64, gsm);
    } else if (t < 768) {
        const int u = t - 256;
        const int pr = u >> 8;
        const int rem = u & 255;
        const int b = rem >> 7;
        const int rt = (rem >> 3) & 15;
        const int ct = rem & 7;
        const int nn = g_nn[b];
        const int nk = g_nk[b];
        const int slot0 = nn + rt * 128;
        if (slot0 >= nk) return;
        gemm16_compact(g_h16 + OFF_EDGES + (size_t)b * EE * EDIM,
                       g_h16 + (pr ? OFF_WEK : OFF_WEQ),
                       pr ? bek : beq, pr ? kp : qp,
                       pr ? 1.f : qscale, EDIM, NN,
                       g_kidx + b * LTOT, slot0, nk, b * HEADS, ct * 64, gsm);
    } else {
        const int u = t - 768;
        if (u < 128) {
            const int row0 = (u >> 3) * 128, col0 = (u & 7) * 64;
            gemm16_body<0, true>(g_h16 + OFF_NODES, g_h16 + OFF_WV, bv, vp, 1.f,
                                 DIMN, INNER, 1024, 1024, 0, 0, row0, col0, 0, gsm);
        } else {
            const int v = u - 128;
            const int row0 = (v >> 3) * 128, col0 = (v & 7) * 64;
            gemm16_body<0, true>(g_h16 + OFF_EDGES, g_h16 + OFF_WEV, bev, vp, 1.f,
                                 EDIM, INNER, 2048, 2048, 0, 1024, row0, col0, 8, gsm);
        }
    }
}

// ---------------------------------------------------------------------------
// Fused output projections. 160 CTAs.
// ---------------------------------------------------------------------------
__global__ __launch_bounds__(256) void outproj_kernel(
        const float* __restrict__ bo, const float* __restrict__ beo,
        float* __restrict__ out) {
    extern __shared__ char gsm[];
    const int t = blockIdx.x;
    if (t < 32) {
        const int col0 = (t & 1) * 64, row0 = (t >> 1) * 128;
        gemm16_body<1, false>(g_oh, g_h16 + OFF_WO, bo, out, 1.f,
                              INNER, DIMN, 1024, 3072, 0, 0, row0, col0, 0, gsm);
    } else {
        const int u = t - 32;
        const int col0 = (u & 3) * 64, row0 = (u >> 2) * 128;
        gemm16_body<1, false>(g_oh, g_h16 + OFF_WEO, beo, out + 2 * 1024 * 128, 1.f,
                              INNER, EDIM, 2048, 3072, 1024, 0, row0, col0, 0, gsm);
    }
}

// ---------------------------------------------------------------------------
// Flash attention over compacted rows (unchanged from R14/R15).
// ---------------------------------------------------------------------------
#define KVSTR 72
#define KVBUF_H (64 * KVSTR)
#define KVBUF_B (KVBUF_H * 2)
#define ATTN_SMEM_BYTES (4 * KVBUF_B)

__device__ __forceinline__ void patch_tiles(int b, int h, int bh, int pstart, int pstep) {
    __shared__ float vms[64];
    const int tid = threadIdx.x;
    if (tid < 64) {
        float s = 0.f;
        #pragma unroll
        for (int c = 0; c < VCH; c++)
            s += g_vpart[((size_t)bh * VCH + c) * DHEAD + tid];
        vms[tid] = s * (1.0f / LTOT);
    }
    __syncthreads();
    const int dg = tid & 7;
    uint4 hv;
    hv.x = packh2(vms[dg * 8 + 0], vms[dg * 8 + 1]);
    hv.y = packh2(vms[dg * 8 + 2], vms[dg * 8 + 3]);
    hv.z = packh2(vms[dg * 8 + 4], vms[dg * 8 + 5]);
    hv.w = packh2(vms[dg * 8 + 6], vms[dg * 8 + 7]);
    for (int p = pstart; p < 24; p += pstep) {
        #pragma unroll
        for (int pass = 0; pass < 4; pass++) {
            int r = p * 128 + pass * 32 + (tid >> 3);
            if (!g_mask[b * LTOT + r])
                *(uint4*)&g_oh[(size_t)(b * LTOT + r) * INNER + h * DHEAD + dg * 8] = hv;
        }
    }
}

__global__ __launch_bounds__(256, 2) void attn_f16_kernel() {
    const int bh = blockIdx.y;
    const int b = bh >> 3, h = bh & 7;
    const int nk = g_nk[b];
    const int q0 = blockIdx.x * 128;
    const int qtiles = (nk + 127) >> 7;
    const int nidle = 24 - qtiles;

    if (q0 >= nk) {
        patch_tiles(b, h, bh, blockIdx.x - qtiles, nidle);
        return;
    }

    extern __shared__ __align__(16) char smraw[];
    __half* Kh = (__half*)smraw;
    __half* Vh = (__half*)(smraw + 2 * KVBUF_B);

    const int tid = threadIdx.x;
    const int warp = tid >> 5, lane = tid & 31;
    const int g = lane >> 2, qd = lane & 3;

    const __half* Qg = g_qh + (size_t)bh * LTOT * DHEAD;
    const __half* Kg = g_kh + (size_t)bh * LTOT * DHEAD;
    const __half* Vg = g_vh + (size_t)bh * LTOT * DHEAD;
    const int* kidx = g_kidx + b * LTOT;
    const int NIT = (nk + 63) >> 6;

    const uint32_t uK = sptr(Kh), uV = sptr(Vh);
    const int offA = ((lane & 7) + ((lane >> 3) & 1) * 8) * 144 + (lane >> 4) * 16;
    const int offK = ((lane & 7) + ((lane >> 4) & 1) * 8) * 144 + ((lane >> 3) & 1) * 16;

    const int prow = tid >> 3;
    const int pch = (tid & 7) * 16;

    {
        #pragma unroll
        for (int rr = 0; rr < 2; rr++) {
            int r = prow + rr * 32;
            int kdrow = (r < nk) ? r : 0;
            int vrow = (r < nk) ? kidx[r] : 0;
            cp16(uK + r * 144 + pch, Kg + (size_t)kdrow * 64 + (pch >> 1));
            cp16(uV + r * 144 + pch, Vg + (size_t)vrow * 64 + (pch >> 1));
        }
        cp_commit();
    }

    const int qr_a = q0 + warp * 16 + g;
    const int qr_b = qr_a + 8;
    const int valid0 = qr_a < nk;
    const int valid1 = qr_b < nk;

    uint32_t qa[4][4];
    {
        const __half* qr0p = Qg + (size_t)(valid0 ? qr_a : 0) * DHEAD;
        const __half* qr1p = Qg + (size_t)(valid1 ? qr_b : 0) * DHEAD;
        #pragma unroll
        for (int kk = 0; kk < 4; kk++) {
            int c = kk * 16 + 2 * qd;
            qa[kk][0] = *(const uint32_t*)(qr0p + c);
            qa[kk][1] = *(const uint32_t*)(qr1p + c);
            qa[kk][2] = *(const uint32_t*)(qr0p + c + 8);
            qa[kk][3] = *(const uint32_t*)(qr1p + c + 8);
        }
    }

    float m_i[2] = {-FLT_MAX, -FLT_MAX};
    float l_i[2] = {0.f, 0.f};
    float o[8][4] = {};

    for (int it = 0; it < NIT; it++) {
        const int bf = it & 1;
        const int k0 = it * 64;
        cp_wait0();
        __syncthreads();

        if (it + 1 < NIT) {
            uint32_t uKn = uK + (bf ^ 1) * KVBUF_B;
            uint32_t uVn = uV + (bf ^ 1) * KVBUF_B;
            #pragma unroll
            for (int rr = 0; rr < 2; rr++) {
                int r = prow + rr * 32;
                int gi = k0 + 64 + r;
                int kdrow = (gi < nk) ? gi : 0;
                int vrow = (gi < nk) ? kidx[gi] : 0;
                cp16(uKn + r * 144 + pch, Kg + (size_t)kdrow * 64 + (pch >> 1));
                cp16(uVn + r * 144 + pch, Vg + (size_t)vrow * 64 + (pch >> 1));
            }
            cp_commit();
        }

        const uint32_t uKb = uK + bf * KVBUF_B;
        const uint32_t uVb = uV + bf * KVBUF_B;

        float s[8][4] = {};
        #pragma unroll
        for (int kk = 0; kk < 4; kk++) {
            #pragma unroll
            for (int p = 0; p < 4; p++) {
                uint32_t b0, b1, b2, b3;
                ldsm_x4(b0, b1, b2, b3, uKb + p * 16 * 144 + kk * 32 + offK);
                mma_f16(s[2 * p],     qa[kk][0], qa[kk][1], qa[kk][2], qa[kk][3], b0, b1);
                mma_f16(s[2 * p + 1], qa[kk][0], qa[kk][1], qa[kk][2], qa[kk][3], b2, b3);
            }
        }

        if (k0 + 64 > nk) {
            #pragma unroll
            for (int nt = 0; nt < 8; nt++) {
                int j0 = k0 + nt * 8 + 2 * qd;
                if (j0 >= nk)     { s[nt][0] = -FLT_MAX; s[nt][2] = -FLT_MAX; }
                if (j0 + 1 >= nk) { s[nt][1] = -FLT_MAX; s[nt][3] = -FLT_MAX; }
            }
        }

        #pragma unroll
        for (int hh = 0; hh < 2; hh++) {
            float mx = -FLT_MAX;
            #pragma unroll
            for (int nt = 0; nt < 8; nt++)
                mx = fmaxf(mx, fmaxf(s[nt][hh * 2], s[nt][hh * 2 + 1]));
            mx = fmaxf(mx, __shfl_xor_sync(0xffffffffu, mx, 1));
            mx = fmaxf(mx, __shfl_xor_sync(0xffffffffu, mx, 2));
            float mnew = fmaxf(m_i[hh], mx);
            float corr = fexp2(m_i[hh] - mnew);
            m_i[hh] = mnew;
            float rs = 0.f;
            #pragma unroll
            for (int nt = 0; nt < 8; nt++) {
                float p0 = fexp2(s[nt][hh * 2]     - mnew);
                float p1 = fexp2(s[nt][hh * 2 + 1] - mnew);
                rs += p0 + p1;
                s[nt][hh * 2]     = p0;
                s[nt][hh * 2 + 1] = p1;
            }
            rs += __shfl_xor_sync(0xffffffffu, rs, 1);
            rs += __shfl_xor_sync(0xffffffffu, rs, 2);
            l_i[hh] = l_i[hh] * corr + rs;
            #pragma unroll
            for (int nt = 0; nt < 8; nt++) {
                o[nt][hh * 2]     *= corr;
                o[nt][hh * 2 + 1] *= corr;
            }
        }

        #pragma unroll
        for (int jj = 0; jj < 4; jj++) {
            uint32_t pa0 = packh2(s[2 * jj][0],     s[2 * jj][1]);
            uint32_t pa1 = packh2(s[2 * jj][2],     s[2 * jj][3]);
            uint32_t pa2 = packh2(s[2 * jj + 1][0], s[2 * jj + 1][1]);
            uint32_t pa3 = packh2(s[2 * jj + 1][2], s[2 * jj + 1][3]);
            #pragma unroll
            for (int p = 0; p < 4; p++) {
                uint32_t b0, b1, b2, b3;
                ldsm_x4_t(b0, b1, b2, b3, uVb + jj * 16 * 144 + p * 32 + offA);
                mma_f16(o[2 * p],     pa0, pa1, pa2, pa3, b0, b1);
                mma_f16(o[2 * p + 1], pa0, pa1, pa2, pa3, b2, b3);
            }
        }
    }

    #pragma unroll
    for (int hh = 0; hh < 2; hh++) {
        if (!(hh ? valid1 : valid0)) continue;
        const int qrow = kidx[hh ? qr_b : qr_a];
        float inv = 1.f / l_i[hh];
        __half* dstp = &g_oh[(size_t)(b * LTOT + qrow) * INNER + h * DHEAD];
        #pragma unroll
        for (int nt = 0; nt < 8; nt++) {
            int d0 = nt * 8 + 2 * qd;
            *(__half2*)&dstp[d0] =
                __floats2half2_rn(o[nt][hh * 2] * inv, o[nt][hh * 2 + 1] * inv);
        }
    }

    if (nidle == 0 && blockIdx.x == 23) {
        __syncthreads();
        patch_tiles(b, h, bh, 0, 1);
    }
}

// ---------------------------------------------------------------------------
// kernel_launch
// ---------------------------------------------------------------------------
extern "C" void kernel_launch(void* const* d_in, const int* in_sizes, int n_in,
                              void* d_out, int out_size) {
    const float* nodes = (const float*)d_in[0];
    const float* edges = (const float*)d_in[1];
    const unsigned char* mask_raw = (const unsigned char*)d_in[2];
    const float* Wq  = (const float*)d_in[3];
    const float* bq  = (const float*)d_in[4];
    const float* Wk  = (const float*)d_in[5];
    const float* bk  = (const float*)d_in[6];
    const float* Wv  = (const float*)d_in[7];
    const float* bv  = (const float*)d_in[8];
    const float* Weq = (const float*)d_in[9];
    const float* beq = (const float*)d_in[10];
    const float* Wek = (const float*)d_in[11];
    const float* bek = (const float*)d_in[12];
    const float* Wev = (const float*)d_in[13];
    const float* bev = (const float*)d_in[14];
    const float* Wo  = (const float*)d_in[15];
    const float* bo  = (const float*)d_in[16];
    const float* Weo = (const float*)d_in[17];
    const float* beo = (const float*)d_in[18];
    float* out = (float*)d_out;

    void *qp, *kp, *vp;
    cudaGetSymbolAddress(&qp, g_qh);
    cudaGetSymbolAddress(&kp, g_kh);
    cudaGetSymbolAddress(&vp, g_vh);

    static bool attrs_set = false;
    if (!attrs_set) {
        cudaFuncSetAttribute(qkv_kernel,
                             cudaFuncAttributeMaxDynamicSharedMemorySize, GEMM_SMEM);
        cudaFuncSetAttribute(outproj_kernel,
                             cudaFuncAttributeMaxDynamicSharedMemorySize, GEMM_SMEM);
        cudaFuncSetAttribute(attn_f16_kernel,
                             cudaFuncAttributeMaxDynamicSharedMemorySize, ATTN_SMEM_BYTES);
        attrs_set = true;
    }

    // Mask decode + compaction + fp32->fp16 conversion of all GEMM operands
    mask_convert_kernel<<<130, 256>>>(mask_raw, nodes, edges,
                                      Wq, Wk, Wv, Weq, Wek, Wev, Wo, Weo);

    // QKV (fp16, cp.async pipelined, BK=64)
    qkv_kernel<<<1152, 256, GEMM_SMEM>>>(bq, bk, bv, beq, bek, bev,
                                         (__half*)qp, (__half*)kp, (__half*)vp,
                                         SCALE * LOG2E);

    // Flash attention + patch in idle CTAs
    attn_f16_kernel<<<dim3(24, BSZ * HEADS), 256, ATTN_SMEM_BYTES>>>();

    // Output projections (fp16 A/W, cp.async pipelined)
    outproj_kernel<<<160, 256, GEMM_SMEM>>>(bo, beo, out);
}

// round 17
// speedup vs baseline: 1.5767x; 1.0524x over previous
#include <cuda_runtime.h>
#include <cuda_fp16.h>
#include <float.h>
#include <math.h>
#include <stdint.h>

// Problem constants
#define BSZ   2
#define NN    1024
#define EE    2048
#define LTOT  3072
#define DIMN  128
#define EDIM  256
#define HEADS 8
#define DHEAD 64
#define INNER 512
#define SCALE 0.125f
#define LOG2E 1.4426950408889634f
#define VCH   24

// fp16 conversion buffer regions (element offsets)
#define OFF_NODES 0
#define OFF_EDGES 262144
#define OFF_WQ    1310720
#define OFF_WK    1376256
#define OFF_WV    1441792
#define OFF_WEQ   1507328
#define OFF_WEK   1638400
#define OFF_WEV   1769472
#define OFF_WO    1900544
#define OFF_WEO   1966080
#define H16_TOTAL 2097152

// Scratch
__device__ __half g_h16[H16_TOTAL];
__device__ __half g_qh[BSZ * HEADS * LTOT * DHEAD];   // COMPACTED rows, pre-scaled
__device__ __half g_kh[BSZ * HEADS * LTOT * DHEAD];   // COMPACTED rows
__device__ __half g_vh[BSZ * HEADS * LTOT * DHEAD];   // full
__device__ __half g_oh[BSZ * LTOT * INNER];
__device__ int    g_mask[BSZ * LTOT];
__device__ int    g_kidx[BSZ * LTOT];
__device__ int    g_nk[BSZ];
__device__ int    g_nn[BSZ];
__device__ float  g_vpart[BSZ * HEADS * VCH * DHEAD];

// ---------------------------------------------------------------------------
// PTX helpers
// ---------------------------------------------------------------------------
__device__ __forceinline__ uint32_t sptr(const void* p) {
    return (uint32_t)__cvta_generic_to_shared(p);
}
__device__ __forceinline__ void ldsm_x4(uint32_t& r0, uint32_t& r1,
                                        uint32_t& r2, uint32_t& r3, uint32_t addr) {
    asm volatile("ldmatrix.sync.aligned.m8n8.x4.shared.b16 {%0,%1,%2,%3}, [%4];"
                 : "=r"(r0), "=r"(r1), "=r"(r2), "=r"(r3) : "r"(addr));
}
__device__ __forceinline__ void ldsm_x4_t(uint32_t& r0, uint32_t& r1,
                                          uint32_t& r2, uint32_t& r3, uint32_t addr) {
    asm volatile("ldmatrix.sync.aligned.m8n8.x4.trans.shared.b16 {%0,%1,%2,%3}, [%4];"
                 : "=r"(r0), "=r"(r1), "=r"(r2), "=r"(r3) : "r"(addr));
}
__device__ __forceinline__ void mma_f16(float c[4],
                                        uint32_t a0, uint32_t a1, uint32_t a2, uint32_t a3,
                                        uint32_t b0, uint32_t b1) {
    asm volatile(
        "mma.sync.aligned.m16n8k16.row.col.f32.f16.f16.f32 "
        "{%0,%1,%2,%3}, {%4,%5,%6,%7}, {%8,%9}, {%0,%1,%2,%3};"
        : "+f"(c[0]), "+f"(c[1]), "+f"(c[2]), "+f"(c[3])
        : "r"(a0), "r"(a1), "r"(a2), "r"(a3), "r"(b0), "r"(b1));
}
__device__ __forceinline__ void cp16(uint32_t dst, const void* src) {
    asm volatile("cp.async.cg.shared.global [%0], [%1], 16;" :: "r"(dst), "l"(src));
}
__device__ __forceinline__ void cp_commit() {
    asm volatile("cp.async.commit_group;");
}
__device__ __forceinline__ void cp_wait0() {
    asm volatile("cp.async.wait_group 0;");
}
__device__ __forceinline__ uint32_t packh2(float x, float y) {
    __half2 h = __floats2half2_rn(x, y);
    return *reinterpret_cast<uint32_t*>(&h);
}
__device__ __forceinline__ float fexp2(float x) {
    float y;
    asm("ex2.approx.ftz.f32 %0, %1;" : "=f"(y) : "f"(x));
    return y;
}

// ---------------------------------------------------------------------------
// Mask decode + compaction (2 CTAs) fused with fp32->fp16 conversion (128 CTAs)
// ---------------------------------------------------------------------------
__global__ __launch_bounds__(256) void mask_convert_kernel(
        const unsigned char* __restrict__ raw,
        const float* nodes, const float* edges,
        const float* Wq, const float* Wk, const float* Wv,
        const float* Weq, const float* Wek, const float* Wev,
        const float* Wo, const float* Weo) {
    const int tid = threadIdx.x;
    if (blockIdx.x < 2) {
        __shared__ int partial[256];
        __shared__ int pfx[256];
        __shared__ int pnode[256];
        const int n = BSZ * LTOT;
        const int b = blockIdx.x;

        int cnt = 0;
        for (int i = tid; i < n; i += 256) cnt += (raw[i] != 0);
        partial[tid] = cnt;
        __syncthreads();
        for (int s = 128; s > 0; s >>= 1) {
            if (tid < s) partial[tid] += partial[tid + s];
            __syncthreads();
        }
        const int width1 = partial[0] > (n * 3 / 8);
        const int* raw32 = (const int*)raw;

        int bits[12];
        int myc = 0, mync = 0;
        #pragma unroll
        for (int i = 0; i < 12; i++) {
            int li = tid * 12 + i;
            int gi = b * LTOT + li;
            int v = width1 ? (raw[gi] != 0) : (raw32[gi] != 0);
            g_mask[gi] = v;
            bits[i] = v;
            myc += v;
            if (li < NN) mync += v;
        }
        pfx[tid] = myc;
        pnode[tid] = mync;
        __syncthreads();
        for (int s = 128; s > 0; s >>= 1) {
            if (tid < s) pnode[tid] += pnode[tid + s];
            __syncthreads();
        }
        if (tid == 0) {
            g_nn[b] = pnode[0];
            int acc = 0;
            for (int t = 0; t < 256; t++) { int c = pfx[t]; pfx[t] = acc; acc += c; }
            g_nk[b] = acc;
        }
        __syncthreads();
        int off = b * LTOT + pfx[tid];
        #pragma unroll
        for (int i = 0; i < 12; i++)
            if (bits[i]) g_kidx[off++] = tid * 12 + i;
    } else {
        const int u = blockIdx.x - 2;
        const float* src; int doff, chunk;
        if      (u < 16)  { src = nodes; doff = OFF_NODES; chunk = u; }
        else if (u < 80)  { src = edges; doff = OFF_EDGES; chunk = u - 16; }
        else if (u < 84)  { src = Wq;    doff = OFF_WQ;    chunk = u - 80; }
        else if (u < 88)  { src = Wk;    doff = OFF_WK;    chunk = u - 84; }
        else if (u < 92)  { src = Wv;    doff = OFF_WV;    chunk = u - 88; }
        else if (u < 100) { src = Weq;   doff = OFF_WEQ;   chunk = u - 92; }
        else if (u < 108) { src = Wek;   doff = OFF_WEK;   chunk = u - 100; }
        else if (u < 116) { src = Wev;   doff = OFF_WEV;   chunk = u - 108; }
        else if (u < 120) { src = Wo;    doff = OFF_WO;    chunk = u - 116; }
        else              { src = Weo;   doff = OFF_WEO;   chunk = u - 120; }
        const int base = chunk * 16384;
        #pragma unroll
        for (int j = 0; j < 16; j++) {
            int e = (j * 256 + tid) * 4;
            float4 v = *(const float4*)(src + base + e);
            uint2 o;
            o.x = packh2(v.x, v.y);
            o.y = packh2(v.z, v.w);
            *(uint2*)(g_h16 + doff + base + e) = o;
        }
    }
}

// ---------------------------------------------------------------------------
// All-fp16 GEMM body: 128x64 tile, BK=64, cp.async double-buffered.
// ---------------------------------------------------------------------------
#define ASTG 18432
#define WSTG 9216
#define GEMM_SMEM (2 * ASTG + 2 * WSTG)

template <int DSTMODE, bool VSUM>
__device__ __forceinline__ void gemm16_body(
        const __half* __restrict__ Ah, const __half* __restrict__ Wh,
        const float* __restrict__ bias, void* __restrict__ dst, float scl,
        int K, int Ncols, int rowsPerBatch, int aBatchStride, int aSeqOff,
        int dstSeqOff, int row0, int col0, int chunkOff, char* smem) {
    const int tid = threadIdx.x;
    const int warp = tid >> 5, lane = tid & 31;
    const int g = lane >> 2, qd = lane & 3;
    const int wy = warp >> 1, wx = warp & 1;

    const uint32_t uA = sptr(smem);
    const uint32_t uW = uA + 2 * ASTG;
    const int offA = ((lane & 7) + ((lane >> 3) & 1) * 8) * 144 + (lane >> 4) * 16;
    const int offW = offA;

    size_t aoff[4];
    int dA[4];
    #pragma unroll
    for (int t = 0; t < 4; t++) {
        int idx = tid + t * 256;
        int i = idx >> 3, c = idx & 7;
        int m = row0 + i;
        int bb = m / rowsPerBatch;
        int r = m - bb * rowsPerBatch;
        aoff[t] = (size_t)(bb * aBatchStride + aSeqOff + r) * K + c * 8;
        dA[t] = i * 144 + c * 16;
    }
    size_t woff[2];
    int dW[2];
    #pragma unroll
    for (int t = 0; t < 2; t++) {
        int idx = tid + t * 256;
        int kr = idx >> 3, c = idx & 7;
        woff[t] = (size_t)kr * Ncols + col0 + c * 8;
        dW[t] = kr * 144 + c * 16;
    }

    const int NIT = K >> 6;
    #pragma unroll
    for (int t = 0; t < 4; t++) cp16(uA + dA[t], Ah + aoff[t]);
    #pragma unroll
    for (int t = 0; t < 2; t++) cp16(uW + dW[t], Wh + woff[t]);
    cp_commit();

    float acc[2][4][4] = {};

    for (int it = 0; it < NIT; it++) {
        const int bf = it & 1;
        cp_wait0();
        __syncthreads();

        if (it + 1 < NIT) {
            const int kt = (it + 1) * 64;
            const uint32_t uAn = uA + (bf ^ 1) * ASTG;
            const uint32_t uWn = uW + (bf ^ 1) * WSTG;
            #pragma unroll
            for (int t = 0; t < 4; t++) cp16(uAn + dA[t], Ah + aoff[t] + kt);
            #pragma unroll
            for (int t = 0; t < 2; t++) cp16(uWn + dW[t], Wh + woff[t] + (size_t)kt * Ncols);
            cp_commit();
        }

        const uint32_t uAb = uA + bf * ASTG;
        const uint32_t uWb = uW + bf * WSTG;
        #pragma unroll
        for (int kk = 0; kk < 4; kk++) {
            uint32_t a[2][4];
            #pragma unroll
            for (int mt = 0; mt < 2; mt++)
                ldsm_x4(a[mt][0], a[mt][1], a[mt][2], a[mt][3],
                        uAb + (wy * 32 + mt * 16) * 144 + kk * 32 + offA);
            #pragma unroll
            for (int p = 0; p < 2; p++) {
                uint32_t b0, b1, b2, b3;
                ldsm_x4_t(b0, b1, b2, b3,
                          uWb + kk * 16 * 144 + (wx * 32 + p * 16) * 2 + offW);
                mma_f16(acc[0][2 * p],     a[0][0], a[0][1], a[0][2], a[0][3], b0, b1);
                mma_f16(acc[0][2 * p + 1], a[0][0], a[0][1], a[0][2], a[0][3], b2, b3);
                mma_f16(acc[1][2 * p],     a[1][0], a[1][1], a[1][2], a[1][3], b0, b1);
                mma_f16(acc[1][2 * p + 1], a[1][0], a[1][1], a[1][2], a[1][3], b2, b3);
            }
        }
    }
    __syncthreads();

    float vsum[4][2];
    if (VSUM) {
        #pragma unroll
        for (int n = 0; n < 4; n++) { vsum[n][0] = 0.f; vsum[n][1] = 0.f; }
    }

    #pragma unroll
    for (int mt = 0; mt < 2; mt++) {
        #pragma unroll
        for (int hh = 0; hh < 2; hh++) {
            int m = row0 + wy * 32 + mt * 16 + g + 8 * hh;
            int bb = m / rowsPerBatch;
            int r = m - bb * rowsPerBatch;
            #pragma unroll
            for (int n = 0; n < 4; n++) {
                int c = col0 + wx * 32 + n * 8 + 2 * qd;
                float v0 = (acc[mt][n][hh * 2 + 0] + bias[c]) * scl;
                float v1 = (acc[mt][n][hh * 2 + 1] + bias[c + 1]) * scl;
                if (VSUM) { vsum[n][0] += v0; vsum[n][1] += v1; }
                if (DSTMODE == 0) {
                    int hidx = c >> 6, d = c & 63;
                    __half* dh = (__half*)dst;
                    *(__half2*)&dh[((size_t)(bb * HEADS + hidx) * LTOT +
                                    dstSeqOff + r) * DHEAD + d] = __floats2half2_rn(v0, v1);
                } else {
                    float* df = (float*)dst;
                    *(float2*)&df[(size_t)m * Ncols + c] = make_float2(v0, v1);
                }
            }
        }
    }

    if (VSUM) {
        #pragma unroll
        for (int n = 0; n < 4; n++)
            #pragma unroll
            for (int e = 0; e < 2; e++) {
                float x = vsum[n][e];
                x += __shfl_xor_sync(0xffffffffu, x, 4);
                x += __shfl_xor_sync(0xffffffffu, x, 8);
                x += __shfl_xor_sync(0xffffffffu, x, 16);
                vsum[n][e] = x;
            }
        float* vs = (float*)smem;
        if (g == 0) {
            #pragma unroll
            for (int n = 0; n < 4; n++) {
                vs[wy * 64 + wx * 32 + n * 8 + 2 * qd + 0] = vsum[n][0];
                vs[wy * 64 + wx * 32 + n * 8 + 2 * qd + 1] = vsum[n][1];
            }
        }
        __syncthreads();
        if (tid < DHEAD) {
            float s = vs[tid] + vs[64 + tid] + vs[128 + tid] + vs[192 + tid];
            int bb = row0 / rowsPerBatch;
            int h = col0 >> 6;
            int chunk = (row0 - bb * rowsPerBatch) / 128 + chunkOff;
            g_vpart[((size_t)(bb * HEADS + h) * VCH + chunk) * DHEAD + tid] = s;
        }
    }
}

// ---------------------------------------------------------------------------
// Compacted-row fp16 GEMM for Q/K projections (gather via kidx).
// ---------------------------------------------------------------------------
__device__ __forceinline__ void gemm16_compact(
        const __half* __restrict__ Ah, const __half* __restrict__ Wh,
        const float* __restrict__ bias, __half* __restrict__ dst, float scl,
        int K, int srcOff, const int* __restrict__ kidx,
        int slot0, int segEnd, int bhBase, int col0, char* smem) {
    const int tid = threadIdx.x;
    const int warp = tid >> 5, lane = tid & 31;
    const int g = lane >> 2, qd = lane & 3;
    const int wy = warp >> 1, wx = warp & 1;

    const uint32_t uA = sptr(smem);
    const uint32_t uW = uA + 2 * ASTG;
    const int offA = ((lane & 7) + ((lane >> 3) & 1) * 8) * 144 + (lane >> 4) * 16;
    const int offW = offA;

    size_t aoff[4];
    int dA[4];
    #pragma unroll
    for (int t = 0; t < 4; t++) {
        int idx = tid + t * 256;
        int i = idx >> 3, c = idx & 7;
        int slot = slot0 + i;
        int src = (slot < segEnd) ? (kidx[slot] - srcOff) : 0;
        aoff[t] = (size_t)src * K + c * 8;
        dA[t] = i * 144 + c * 16;
    }
    size_t woff[2];
    int dW[2];
    #pragma unroll
    for (int t = 0; t < 2; t++) {
        int idx = tid + t * 256;
        int kr = idx >> 3, c = idx & 7;
        woff[t] = (size_t)kr * INNER + col0 + c * 8;
        dW[t] = kr * 144 + c * 16;
    }

    const int NIT = K >> 6;
    #pragma unroll
    for (int t = 0; t < 4; t++) cp16(uA + dA[t], Ah + aoff[t]);
    #pragma unroll
    for (int t = 0; t < 2; t++) cp16(uW + dW[t], Wh + woff[t]);
    cp_commit();

    float acc[2][4][4] = {};

    for (int it = 0; it < NIT; it++) {
        const int bf = it & 1;
        cp_wait0();
        __syncthreads();

        if (it + 1 < NIT) {
            const int kt = (it + 1) * 64;
            const uint32_t uAn = uA + (bf ^ 1) * ASTG;
            const uint32_t uWn = uW + (bf ^ 1) * WSTG;
            #pragma unroll
            for (int t = 0; t < 4; t++) cp16(uAn + dA[t], Ah + aoff[t] + kt);
            #pragma unroll
            for (int t = 0; t < 2; t++) cp16(uWn + dW[t], Wh + woff[t] + (size_t)kt * INNER);
            cp_commit();
        }

        const uint32_t uAb = uA + bf * ASTG;
        const uint32_t uWb = uW + bf * WSTG;
        #pragma unroll
        for (int kk = 0; kk < 4; kk++) {
            uint32_t a[2][4];
            #pragma unroll
            for (int mt = 0; mt < 2; mt++)
                ldsm_x4(a[mt][0], a[mt][1], a[mt][2], a[mt][3],
                        uAb + (wy * 32 + mt * 16) * 144 + kk * 32 + offA);
            #pragma unroll
            for (int p = 0; p < 2; p++) {
                uint32_t b0, b1, b2, b3;
                ldsm_x4_t(b0, b1, b2, b3,
                          uWb + kk * 16 * 144 + (wx * 32 + p * 16) * 2 + offW);
                mma_f16(acc[0][2 * p],     a[0][0], a[0][1], a[0][2], a[0][3], b0, b1);
                mma_f16(acc[0][2 * p + 1], a[0][0], a[0][1], a[0][2], a[0][3], b2, b3);
                mma_f16(acc[1][2 * p],     a[1][0], a[1][1], a[1][2], a[1][3], b0, b1);
                mma_f16(acc[1][2 * p + 1], a[1][0], a[1][1], a[1][2], a[1][3], b2, b3);
            }
        }
    }

    #pragma unroll
    for (int mt = 0; mt < 2; mt++) {
        #pragma unroll
        for (int hh = 0; hh < 2; hh++) {
            int slot = slot0 + wy * 32 + mt * 16 + g + 8 * hh;
            bool ok = slot < segEnd;
            #pragma unroll
            for (int n = 0; n < 4; n++) {
                int c = col0 + wx * 32 + n * 8 + 2 * qd;
                float v0 = (acc[mt][n][hh * 2 + 0] + bias[c]) * scl;
                float v1 = (acc[mt][n][hh * 2 + 1] + bias[c + 1]) * scl;
                if (ok) {
                    int hidx = c >> 6, d = c & 63;
                    *(__half2*)&dst[((size_t)(bhBase + hidx) * LTOT + slot) * DHEAD + d] =
                        __floats2half2_rn(v0, v1);
                }
            }
        }
    }
}

// ---------------------------------------------------------------------------
// Fused QKV projections: Q/K compacted, V dense (+fused vpart reduction).
// ---------------------------------------------------------------------------
__global__ __launch_bounds__(256) void qkv_kernel(
        const float* bq, const float* bk, const float* bv,
        const float* beq, const float* bek, const float* bev,
        __half* qp, __half* kp, __half* vp, float qscale) {
    extern __shared__ char gsm[];
    const int t = blockIdx.x;
    if (t < 256) {
        const int pr = t >> 7;
        const int rem = t & 127;
        const int b = rem >> 6;
        const int rt = (rem >> 3) & 7;
        const int ct = rem & 7;
        const int nn = g_nn[b];
        const int slot0 = rt * 128;
        if (slot0 >= nn) return;
        gemm16_compact(g_h16 + OFF_NODES + (size_t)b * NN * DIMN,
                       g_h16 + (pr ? OFF_WK : OFF_WQ),
                       pr ? bk : bq, pr ? kp : qp,
                       pr ? 1.f : qscale, DIMN, 0,
                       g_kidx + b * LTOT, slot0, nn, b * HEADS, ct * 64, gsm);
    } else if (t < 768) {
        const int u = t - 256;
        const int pr = u >> 8;
        const int rem = u & 255;
        const int b = rem >> 7;
        const int rt = (rem >> 3) & 15;
        const int ct = rem & 7;
        const int nn = g_nn[b];
        const int nk = g_nk[b];
        const int slot0 = nn + rt * 128;
        if (slot0 >= nk) return;
        gemm16_compact(g_h16 + OFF_EDGES + (size_t)b * EE * EDIM,
                       g_h16 + (pr ? OFF_WEK : OFF_WEQ),
                       pr ? bek : beq, pr ? kp : qp,
                       pr ? 1.f : qscale, EDIM, NN,
                       g_kidx + b * LTOT, slot0, nk, b * HEADS, ct * 64, gsm);
    } else {
        const int u = t - 768;
        if (u < 128) {
            const int row0 = (u >> 3) * 128, col0 = (u & 7) * 64;
            gemm16_body<0, true>(g_h16 + OFF_NODES, g_h16 + OFF_WV, bv, vp, 1.f,
                                 DIMN, INNER, 1024, 1024, 0, 0, row0, col0, 0, gsm);
        } else {
            const int v = u - 128;
            const int row0 = (v >> 3) * 128, col0 = (v & 7) * 64;
            gemm16_body<0, true>(g_h16 + OFF_EDGES, g_h16 + OFF_WEV, bev, vp, 1.f,
                                 EDIM, INNER, 2048, 2048, 0, 1024, row0, col0, 8, gsm);
        }
    }
}

// ---------------------------------------------------------------------------
// Fused output projections. 160 CTAs.
// ---------------------------------------------------------------------------
__global__ __launch_bounds__(256) void outproj_kernel(
        const float* __restrict__ bo, const float* __restrict__ beo,
        float* __restrict__ out) {
    extern __shared__ char gsm[];
    const int t = blockIdx.x;
    if (t < 32) {
        const int col0 = (t & 1) * 64, row0 = (t >> 1) * 128;
        gemm16_body<1, false>(g_oh, g_h16 + OFF_WO, bo, out, 1.f,
                              INNER, DIMN, 1024, 3072, 0, 0, row0, col0, 0, gsm);
    } else {
        const int u = t - 32;
        const int col0 = (u & 3) * 64, row0 = (u >> 2) * 128;
        gemm16_body<1, false>(g_oh, g_h16 + OFF_WEO, beo, out + 2 * 1024 * 128, 1.f,
                              INNER, EDIM, 2048, 3072, 1024, 0, row0, col0, 0, gsm);
    }
}

// ---------------------------------------------------------------------------
// Flash attention, Br=192 (384 threads, 12 warps), Bc=64, compacted rows.
// 128 active compute CTAs ~= one wave. Loader = threads 0..255 only.
// Idle CTAs patch masked rows of g_oh from g_vpart.
// ---------------------------------------------------------------------------
#define KVSTR 72
#define KVBUF_H (64 * KVSTR)
#define KVBUF_B (KVBUF_H * 2)
#define ATTN_SMEM_BYTES (4 * KVBUF_B)
#define BR 192
#define QT 16                                    // LTOT / BR

__device__ __forceinline__ void patch_tiles(int b, int h, int bh, int pstart, int pstep) {
    __shared__ float vms[64];
    const int tid = threadIdx.x;
    if (tid < 64) {
        float s = 0.f;
        #pragma unroll
        for (int c = 0; c < VCH; c++)
            s += g_vpart[((size_t)bh * VCH + c) * DHEAD + tid];
        vms[tid] = s * (1.0f / LTOT);
    }
    __syncthreads();
    if (tid < 256) {
        const int dg = tid & 7;
        uint4 hv;
        hv.x = packh2(vms[dg * 8 + 0], vms[dg * 8 + 1]);
        hv.y = packh2(vms[dg * 8 + 2], vms[dg * 8 + 3]);
        hv.z = packh2(vms[dg * 8 + 4], vms[dg * 8 + 5]);
        hv.w = packh2(vms[dg * 8 + 6], vms[dg * 8 + 7]);
        for (int p = pstart; p < 24; p += pstep) {
            #pragma unroll
            for (int pass = 0; pass < 4; pass++) {
                int r = p * 128 + pass * 32 + (tid >> 3);
                if (!g_mask[b * LTOT + r])
                    *(uint4*)&g_oh[(size_t)(b * LTOT + r) * INNER + h * DHEAD + dg * 8] = hv;
            }
        }
    }
}

__global__ __launch_bounds__(384, 1) void attn_f16_kernel() {
    const int bh = blockIdx.y;
    const int b = bh >> 3, h = bh & 7;
    const int nk = g_nk[b];
    const int q0 = blockIdx.x * BR;
    const int qtiles = (nk + BR - 1) / BR;
    const int nidle = QT - qtiles;

    if (q0 >= nk) {
        patch_tiles(b, h, bh, blockIdx.x - qtiles, nidle);
        return;
    }

    extern __shared__ __align__(16) char smraw[];
    __half* Kh = (__half*)smraw;
    __half* Vh = (__half*)(smraw + 2 * KVBUF_B);

    const int tid = threadIdx.x;
    const int warp = tid >> 5, lane = tid & 31;
    const int g = lane >> 2, qd = lane & 3;

    const __half* Qg = g_qh + (size_t)bh * LTOT * DHEAD;
    const __half* Kg = g_kh + (size_t)bh * LTOT * DHEAD;
    const __half* Vg = g_vh + (size_t)bh * LTOT * DHEAD;
    const int* kidx = g_kidx + b * LTOT;
    const int NIT = (nk + 63) >> 6;

    const uint32_t uK = sptr(Kh), uV = sptr(Vh);
    const int offA = ((lane & 7) + ((lane >> 3) & 1) * 8) * 144 + (lane >> 4) * 16;
    const int offK = ((lane & 7) + ((lane >> 4) & 1) * 8) * 144 + ((lane >> 3) & 1) * 16;

    const int prow = tid >> 3;                   // loader threads: 0..31
    const int pch = (tid & 7) * 16;
    const bool loader = tid < 256;

    // Prologue: load tile 0 (K dense, V gathered)
    if (loader) {
        #pragma unroll
        for (int rr = 0; rr < 2; rr++) {
            int r = prow + rr * 32;
            int kdrow = (r < nk) ? r : 0;
            int vrow = (r < nk) ? kidx[r] : 0;
            cp16(uK + r * 144 + pch, Kg + (size_t)kdrow * 64 + (pch >> 1));
            cp16(uV + r * 144 + pch, Vg + (size_t)vrow * 64 + (pch >> 1));
        }
    }
    cp_commit();

    // Query rows: dense compacted slots (warp 0..11 x 16 rows = 192)
    const int qr_a = q0 + warp * 16 + g;
    const int qr_b = qr_a + 8;
    const int valid0 = qr_a < nk;
    const int valid1 = qr_b < nk;

    uint32_t qa[4][4];
    {
        const __half* qr0p = Qg + (size_t)(valid0 ? qr_a : 0) * DHEAD;
        const __half* qr1p = Qg + (size_t)(valid1 ? qr_b : 0) * DHEAD;
        #pragma unroll
        for (int kk = 0; kk < 4; kk++) {
            int c = kk * 16 + 2 * qd;
            qa[kk][0] = *(const uint32_t*)(qr0p + c);
            qa[kk][1] = *(const uint32_t*)(qr1p + c);
            qa[kk][2] = *(const uint32_t*)(qr0p + c + 8);
            qa[kk][3] = *(const uint32_t*)(qr1p + c + 8);
        }
    }

    float m_i[2] = {-FLT_MAX, -FLT_MAX};
    float l_i[2] = {0.f, 0.f};
    float o[8][4] = {};

    for (int it = 0; it < NIT; it++) {
        const int bf = it & 1;
        const int k0 = it * 64;
        cp_wait0();
        __syncthreads();

        if (it + 1 < NIT) {
            if (loader) {
                uint32_t uKn = uK + (bf ^ 1) * KVBUF_B;
                uint32_t uVn = uV + (bf ^ 1) * KVBUF_B;
                #pragma unroll
                for (int rr = 0; rr < 2; rr++) {
                    int r = prow + rr * 32;
                    int gi = k0 + 64 + r;
                    int kdrow = (gi < nk) ? gi : 0;
                    int vrow = (gi < nk) ? kidx[gi] : 0;
                    cp16(uKn + r * 144 + pch, Kg + (size_t)kdrow * 64 + (pch >> 1));
                    cp16(uVn + r * 144 + pch, Vg + (size_t)vrow * 64 + (pch >> 1));
                }
            }
            cp_commit();
        }

        const uint32_t uKb = uK + bf * KVBUF_B;
        const uint32_t uVb = uV + bf * KVBUF_B;

        float s[8][4] = {};
        #pragma unroll
        for (int kk = 0; kk < 4; kk++) {
            #pragma unroll
            for (int p = 0; p < 4; p++) {
                uint32_t b0, b1, b2, b3;
                ldsm_x4(b0, b1, b2, b3, uKb + p * 16 * 144 + kk * 32 + offK);
                mma_f16(s[2 * p],     qa[kk][0], qa[kk][1], qa[kk][2], qa[kk][3], b0, b1);
                mma_f16(s[2 * p + 1], qa[kk][0], qa[kk][1], qa[kk][2], qa[kk][3], b2, b3);
            }
        }

        if (k0 + 64 > nk) {
            #pragma unroll
            for (int nt = 0; nt < 8; nt++) {
                int j0 = k0 + nt * 8 + 2 * qd;
                if (j0 >= nk)     { s[nt][0] = -FLT_MAX; s[nt][2] = -FLT_MAX; }
                if (j0 + 1 >= nk) { s[nt][1] = -FLT_MAX; s[nt][3] = -FLT_MAX; }
            }
        }

        #pragma unroll
        for (int hh = 0; hh < 2; hh++) {
            float mx = -FLT_MAX;
            #pragma unroll
            for (int nt = 0; nt < 8; nt++)
                mx = fmaxf(mx, fmaxf(s[nt][hh * 2], s[nt][hh * 2 + 1]));
            mx = fmaxf(mx, __shfl_xor_sync(0xffffffffu, mx, 1));
            mx = fmaxf(mx, __shfl_xor_sync(0xffffffffu, mx, 2));
            float mnew = fmaxf(m_i[hh], mx);
            float corr = fexp2(m_i[hh] - mnew);
            m_i[hh] = mnew;
            float rs = 0.f;
            #pragma unroll
            for (int nt = 0; nt < 8; nt++) {
                float p0 = fexp2(s[nt][hh * 2]     - mnew);
                float p1 = fexp2(s[nt][hh * 2 + 1] - mnew);
                rs += p0 + p1;
                s[nt][hh * 2]     = p0;
                s[nt][hh * 2 + 1] = p1;
            }
            rs += __shfl_xor_sync(0xffffffffu, rs, 1);
            rs += __shfl_xor_sync(0xffffffffu, rs, 2);
            l_i[hh] = l_i[hh] * corr + rs;
            #pragma unroll
            for (int nt = 0; nt < 8; nt++) {
                o[nt][hh * 2]     *= corr;
                o[nt][hh * 2 + 1] *= corr;
            }
        }

        #pragma unroll
        for (int jj = 0; jj < 4; jj++) {
            uint32_t pa0 = packh2(s[2 * jj][0],     s[2 * jj][1]);
            uint32_t pa1 = packh2(s[2 * jj][2],     s[2 * jj][3]);
            uint32_t pa2 = packh2(s[2 * jj + 1][0], s[2 * jj + 1][1]);
            uint32_t pa3 = packh2(s[2 * jj + 1][2], s[2 * jj + 1][3]);
            #pragma unroll
            for (int p = 0; p < 4; p++) {
                uint32_t b0, b1, b2, b3;
                ldsm_x4_t(b0, b1, b2, b3, uVb + jj * 16 * 144 + p * 32 + offA);
                mma_f16(o[2 * p],     pa0, pa1, pa2, pa3, b0, b1);
                mma_f16(o[2 * p + 1], pa0, pa1, pa2, pa3, b2, b3);
            }
        }
    }

    #pragma unroll
    for (int hh = 0; hh < 2; hh++) {
        if (!(hh ? valid1 : valid0)) continue;
        const int qrow = kidx[hh ? qr_b : qr_a];
        float inv = 1.f / l_i[hh];
        __half* dstp = &g_oh[(size_t)(b * LTOT + qrow) * INNER + h * DHEAD];
        #pragma unroll
        for (int nt = 0; nt < 8; nt++) {
            int d0 = nt * 8 + 2 * qd;
            *(__half2*)&dstp[d0] =
                __floats2half2_rn(o[nt][hh * 2] * inv, o[nt][hh * 2 + 1] * inv);
        }
    }

    if (nidle == 0 && blockIdx.x == QT - 1) {
        __syncthreads();
        patch_tiles(b, h, bh, 0, 1);
    }
}

// ---------------------------------------------------------------------------
// kernel_launch
// ---------------------------------------------------------------------------
extern "C" void kernel_launch(void* const* d_in, const int* in_sizes, int n_in,
                              void* d_out, int out_size) {
    const float* nodes = (const float*)d_in[0];
    const float* edges = (const float*)d_in[1];
    const unsigned char* mask_raw = (const unsigned char*)d_in[2];
    const float* Wq  = (const float*)d_in[3];
    const float* bq  = (const float*)d_in[4];
    const float* Wk  = (const float*)d_in[5];
    const float* bk  = (const float*)d_in[6];
    const float* Wv  = (const float*)d_in[7];
    const float* bv  = (const float*)d_in[8];
    const float* Weq = (const float*)d_in[9];
    const float* beq = (const float*)d_in[10];
    const float* Wek = (const float*)d_in[11];
    const float* bek = (const float*)d_in[12];
    const float* Wev = (const float*)d_in[13];
    const float* bev = (const float*)d_in[14];
    const float* Wo  = (const float*)d_in[15];
    const float* bo  = (const float*)d_in[16];
    const float* Weo = (const float*)d_in[17];
    const float* beo = (const float*)d_in[18];
    float* out = (float*)d_out;

    void *qp, *kp, *vp;
    cudaGetSymbolAddress(&qp, g_qh);
    cudaGetSymbolAddress(&kp, g_kh);
    cudaGetSymbolAddress(&vp, g_vh);

    static bool attrs_set = false;
    if (!attrs_set) {
        cudaFuncSetAttribute(qkv_kernel,
                             cudaFuncAttributeMaxDynamicSharedMemorySize, GEMM_SMEM);
        cudaFuncSetAttribute(outproj_kernel,
                             cudaFuncAttributeMaxDynamicSharedMemorySize, GEMM_SMEM);
        cudaFuncSetAttribute(attn_f16_kernel,
                             cudaFuncAttributeMaxDynamicSharedMemorySize, ATTN_SMEM_BYTES);
        attrs_set = true;
    }

    mask_convert_kernel<<<130, 256>>>(mask_raw, nodes, edges,
                                      Wq, Wk, Wv, Weq, Wek, Wev, Wo, Weo);

    qkv_kernel<<<1152, 256, GEMM_SMEM>>>(bq, bk, bv, beq, bek, bev,
                                         (__half*)qp, (__half*)kp, (__half*)vp,
                                         SCALE * LOG2E);

    attn_f16_kernel<<<dim3(QT, BSZ * HEADS), 384, ATTN_SMEM_BYTES>>>();

    outproj_kernel<<<160, 256, GEMM_SMEM>>>(bo, beo, out);
}